// round 10
// baseline (speedup 1.0000x reference)
#include <cuda_runtime.h>
#include <cuda_bf16.h>
#include <math.h>

// ---------------------------------------------------------------------------
// MultiDEQPDEBlock: DEQ fixed-point PDE solver  (B=8, 256x256, hid=32, GN4)
// core_f: conv3x3(4->32) -> GN(4) -> GELU(erf) -> conv3x3(32->1) -> damped update
// h_fixed (conv of loop-invariant [b,m,k]) precomputed once; per-iter conv1 is
// the 9-tap z convolution. fused2: FILL4 staging + const-offset conv loop +
// launch_bounds(256,4) -> 64-reg cap, 4 blocks/SM (occ ~50%).
// Divergent dynamics (|1-mask|>1) -> ~1e37; overflow paths mirror jax
// (var->inf, rstd->0, xn->0; NaN diff stops loop).
// ---------------------------------------------------------------------------

#define BATCH 8
#define HH 256
#define WW 256
#define PIX (HH*WW)
#define HID 32
#define SHID 16
#define GROUPS 4
#define CPG 8
#define EPS 1e-5f
#define TOL 1e-4f
#define MAX_ITER 50
#define CFL_SCALE 0.015625f
#define NBLK 2048               // (16,16,8) grids

// ---- scratch (device globals; no cudaMalloc allowed) ----
__device__ float g_h[(size_t)BATCH*HID*PIX];      // 64 MB conv1 output (pre-GN)
__device__ float g_hfix[(size_t)BATCH*HID*PIX];   // 64 MB conv of fixed channels
__device__ float g_sh[(size_t)BATCH*SHID*PIX];    // 32 MB stabilizer hidden
__device__ float g_alpha[(size_t)BATCH*PIX];
__device__ float g_z[(size_t)BATCH*PIX];
__device__ float g_gamma[BATCH];
__device__ float g_part[BATCH*256*GROUPS*2];
__device__ float g_spart[BATCH*256*4];
__device__ float g_scale[BATCH*HID];
__device__ float g_shift[BATCH*HID];
__device__ float g_diffpart[BATCH*256];
__device__ int   g_converged;
__device__ unsigned g_cnt0;     // zero-init; self-resetting via atomicInc wrap
__device__ unsigned g_cnt1;
__device__ unsigned g_cnt2;

__device__ __forceinline__ float gelu_f(float x) {
    return 0.5f * x * (1.0f + erff(x * 0.70710678118654752f));
}
__device__ __forceinline__ float sigmoid_f(float x) {
    return 1.0f / (1.0f + expf(-x));
}

// ---------------------------------------------------------------------------
// stabilizer conv1 (3->16, GELU) + z init + spec partials; last block: gamma MLP
// ---------------------------------------------------------------------------
__global__ void __launch_bounds__(256) stab1_kernel(
    const float* __restrict__ inp, const float* __restrict__ w,
    const float* __restrict__ bias,
    const float* __restrict__ fc1_w, const float* __restrict__ fc1_b,
    const float* __restrict__ fc2_w, const float* __restrict__ fc2_b)
{
    const int b = blockIdx.z;
    const int tx0 = blockIdx.x * 16, ty0 = blockIdx.y * 16;
    __shared__ float s_in[3][18][18];
    __shared__ float s_w[27][16];
    __shared__ float s_b[16];
    __shared__ float s_red[8][4];
    __shared__ bool s_last;
    int tid = threadIdx.y * 16 + threadIdx.x;

    if (tid == 0 && blockIdx.x == 0 && blockIdx.y == 0 && b == 0) g_converged = 0;

    for (int i = tid; i < SHID * 27; i += 256) {
        int oc = i / 27, r = i % 27;
        s_w[r][oc] = w[i];
    }
    if (tid < SHID) s_b[tid] = bias[tid];

    const float* bp = inp + (size_t)b * 3 * PIX;
    for (int i = tid; i < 3 * 324; i += 256) {
        int c = i / 324, r = i % 324, yy = r / 18, xx = r % 18;
        int gy = ty0 + yy - 1, gx = tx0 + xx - 1;
        float v = 0.f;
        if ((unsigned)gy < 256u && (unsigned)gx < 256u)
            v = bp[c * PIX + gy * WW + gx];
        s_in[c][yy][xx] = v;
    }
    __syncthreads();

    int ty = threadIdx.y, tx = threadIdx.x;
    float in[27];
#pragma unroll
    for (int c = 0; c < 3; c++)
#pragma unroll
        for (int ky = 0; ky < 3; ky++)
#pragma unroll
            for (int kx = 0; kx < 3; kx++)
                in[c * 9 + ky * 3 + kx] = s_in[c][ty + ky][tx + kx];

    float acc[SHID];
#pragma unroll
    for (int oc = 0; oc < SHID; oc++) acc[oc] = s_b[oc];
#pragma unroll
    for (int r = 0; r < 27; r++) {
        float iv = in[r];
#pragma unroll
        for (int oc = 0; oc < SHID; oc++) acc[oc] += iv * s_w[r][oc];
    }

    int pix = (ty0 + ty) * WW + (tx0 + tx);
    float* out = g_sh + (size_t)b * SHID * PIX + pix;
#pragma unroll
    for (int oc = 0; oc < SHID; oc++)
        out[oc * PIX] = gelu_f(acc[oc]);

    // z init (channel 0 = boundary)
    g_z[b * PIX + pix] = s_in[0][ty + 1][tx + 1];

    // spec partials: |boundary| and k stats
    float bv = fabsf(s_in[0][ty + 1][tx + 1]);
    float kv = s_in[2][ty + 1][tx + 1];
    float s1 = bv, q1 = bv * bv, s2 = kv, q2 = kv * kv;
#pragma unroll
    for (int o = 16; o > 0; o >>= 1) {
        s1 += __shfl_down_sync(0xffffffffu, s1, o);
        q1 += __shfl_down_sync(0xffffffffu, q1, o);
        s2 += __shfl_down_sync(0xffffffffu, s2, o);
        q2 += __shfl_down_sync(0xffffffffu, q2, o);
    }
    int lane = tid & 31, warp = tid >> 5;
    if (lane == 0) { s_red[warp][0] = s1; s_red[warp][1] = q1; s_red[warp][2] = s2; s_red[warp][3] = q2; }
    __syncthreads();
    int blin = blockIdx.y * 16 + blockIdx.x;
    if (tid < 4) {
        float v = 0.f;
#pragma unroll
        for (int w8 = 0; w8 < 8; w8++) v += s_red[w8][tid];
        g_spart[(b * 256 + blin) * 4 + tid] = v;
        __threadfence();
    }
    __syncthreads();
    if (tid == 0) {
        unsigned old = atomicInc(&g_cnt0, NBLK - 1u);
        s_last = (old == NBLK - 1u);
    }
    __syncthreads();
    if (!s_last) return;
    __threadfence();

    // last block: per-batch spec_ctrl MLP -> gamma (warp w = batch w)
    int w8 = tid >> 5, l = tid & 31;
    float S1 = 0, Q1 = 0, S2 = 0, Q2 = 0;
    for (int i = l; i < 256; i += 32) {
        S1 += g_spart[(w8 * 256 + i) * 4 + 0];
        Q1 += g_spart[(w8 * 256 + i) * 4 + 1];
        S2 += g_spart[(w8 * 256 + i) * 4 + 2];
        Q2 += g_spart[(w8 * 256 + i) * 4 + 3];
    }
#pragma unroll
    for (int o = 16; o > 0; o >>= 1) {
        S1 += __shfl_down_sync(0xffffffffu, S1, o);
        Q1 += __shfl_down_sync(0xffffffffu, Q1, o);
        S2 += __shfl_down_sync(0xffffffffu, S2, o);
        Q2 += __shfl_down_sync(0xffffffffu, Q2, o);
    }
    if (l == 0) {
        const float N = (float)PIX;
        float m1 = S1 / N, m2 = S2 / N;
        float v1 = (Q1 - N * m1 * m1) / (N - 1.0f);
        float v2 = (Q2 - N * m2 * m2) / (N - 1.0f);
        float feat[5] = { m1, sqrtf(fmaxf(v1, 0.f)), m2, sqrtf(fmaxf(v2, 0.f)), 1.0f };
        float outv = fc2_b[0];
        for (int j = 0; j < 32; j++) {
            float t = fc1_b[j];
#pragma unroll
            for (int i = 0; i < 5; i++) t += feat[i] * fc1_w[j * 5 + i];
            outv += gelu_f(t) * fc2_w[j];
        }
        g_gamma[w8] = (0.5f + 1.5f * sigmoid_f(outv)) * CFL_SCALE;
    }
}

// ---------------------------------------------------------------------------
// prep: stab2 (16->1 sigmoid -> alpha)  AND  hfix (conv3x3 of [b,m,k] + bias)
// ---------------------------------------------------------------------------
__global__ void __launch_bounds__(256) prep_kernel(
    const float* __restrict__ inp,
    const float* __restrict__ w2s, const float* __restrict__ b2s,
    const float* __restrict__ w1, const float* __restrict__ b1)
{
    const int b = blockIdx.z;
    const int tx0 = blockIdx.x * 16, ty0 = blockIdx.y * 16;
    __shared__ float s_sh[SHID][18][18];
    __shared__ float s_in[3][18][18];
    __shared__ float s_ws[SHID * 9];
    __shared__ __align__(16) float s_wh[27][32];
    __shared__ float s_bh[32];
    int tid = threadIdx.y * 16 + threadIdx.x;

    if (tid < SHID * 9) s_ws[tid] = w2s[tid];
    for (int i = tid; i < HID * 27; i += 256) {
        int oc = i / 27, r = i % 27;
        s_wh[r][oc] = w1[oc * 36 + 9 + r];   // skip z-channel taps
    }
    if (tid < HID) s_bh[tid] = b1[tid];

    const float* hp = g_sh + (size_t)b * SHID * PIX;
    for (int i = tid; i < SHID * 324; i += 256) {
        int c = i / 324, r = i % 324, yy = r / 18, xx = r % 18;
        int gy = ty0 + yy - 1, gx = tx0 + xx - 1;
        float v = 0.f;
        if ((unsigned)gy < 256u && (unsigned)gx < 256u)
            v = hp[c * PIX + gy * WW + gx];
        s_sh[c][yy][xx] = v;
    }
    const float* bp = inp + (size_t)b * 3 * PIX;
    for (int i = tid; i < 3 * 324; i += 256) {
        int c = i / 324, r = i % 324, yy = r / 18, xx = r % 18;
        int gy = ty0 + yy - 1, gx = tx0 + xx - 1;
        float v = 0.f;
        if ((unsigned)gy < 256u && (unsigned)gx < 256u)
            v = bp[c * PIX + gy * WW + gx];
        s_in[c][yy][xx] = v;
    }
    __syncthreads();

    int ty = threadIdx.y, tx = threadIdx.x;
    int pix = (ty0 + ty) * WW + (tx0 + tx);

    // stab2: alpha
    {
        float acc = b2s[0];
#pragma unroll
        for (int c = 0; c < SHID; c++)
#pragma unroll
            for (int ky = 0; ky < 3; ky++)
#pragma unroll
                for (int kx = 0; kx < 3; kx++)
                    acc += s_ws[c * 9 + ky * 3 + kx] * s_sh[c][ty + ky][tx + kx];
        g_alpha[(size_t)b * PIX + pix] = sigmoid_f(acc);
    }

    // hfix: 27-tap conv of fixed channels into 32 outputs
    {
        float acc[HID];
#pragma unroll
        for (int oc = 0; oc < HID; oc++) acc[oc] = s_bh[oc];
#pragma unroll
        for (int c = 0; c < 3; c++)
#pragma unroll
            for (int ky = 0; ky < 3; ky++)
#pragma unroll
                for (int kx = 0; kx < 3; kx++) {
                    float iv = s_in[c][ty + ky][tx + kx];
                    int r = c * 9 + ky * 3 + kx;
#pragma unroll
                    for (int j = 0; j < 8; j++) {
                        float4 w4 = ((const float4*)&s_wh[r][0])[j];
                        acc[4*j+0] += iv * w4.x; acc[4*j+1] += iv * w4.y;
                        acc[4*j+2] += iv * w4.z; acc[4*j+3] += iv * w4.w;
                    }
                }
        float* op = g_hfix + (size_t)b * HID * PIX + pix;
#pragma unroll
        for (int oc = 0; oc < HID; oc++) op[oc * PIX] = acc[oc];
    }
}

// ---------------------------------------------------------------------------
// convz: h = h_fixed + conv3x3(z, w1[:,0])  (9 taps), write g_h + GN partials;
// LAST BLOCK folds GN stats -> scale/shift.
// ---------------------------------------------------------------------------
__global__ void __launch_bounds__(256, 4) convz_kernel(
    const float* __restrict__ w1, const float* __restrict__ gn_w,
    const float* __restrict__ gn_b, int check)
{
    if (check && g_converged) return;
    const int b = blockIdx.z;
    const int tx0 = blockIdx.x * 16, ty0 = blockIdx.y * 16;
    __shared__ float s_z[18][18];
    __shared__ __align__(16) float s_w[9][32];
    __shared__ float s_red[8][8];
    __shared__ bool s_last;
    int tid = threadIdx.y * 16 + threadIdx.x;

    for (int i = tid; i < HID * 9; i += 256) {
        int oc = i / 9, r = i % 9;
        s_w[r][oc] = w1[oc * 36 + r];       // z-channel taps (c=0)
    }

    const float* zp = g_z + b * PIX;
    for (int i = tid; i < 324; i += 256) {
        int yy = i / 18, xx = i % 18;
        int gy = ty0 + yy - 1, gx = tx0 + xx - 1;
        float v = 0.f;
        if ((unsigned)gy < 256u && (unsigned)gx < 256u)
            v = zp[gy * WW + gx];
        s_z[yy][xx] = v;
    }
    __syncthreads();

    int ty = threadIdx.y, tx = threadIdx.x;
    float zv[9];
#pragma unroll
    for (int ky = 0; ky < 3; ky++)
#pragma unroll
        for (int kx = 0; kx < 3; kx++)
            zv[ky * 3 + kx] = s_z[ty + ky][tx + kx];

    int pix = (ty0 + ty) * WW + (tx0 + tx);
    const float* fp = g_hfix + (size_t)b * HID * PIX + pix;
    float acc[HID];
#pragma unroll
    for (int oc = 0; oc < HID; oc++) acc[oc] = fp[oc * PIX];
#pragma unroll
    for (int r = 0; r < 9; r++) {
        float iv = zv[r];
#pragma unroll
        for (int j = 0; j < 8; j++) {
            float4 w4 = ((const float4*)&s_w[r][0])[j];
            acc[4*j+0] += iv * w4.x; acc[4*j+1] += iv * w4.y;
            acc[4*j+2] += iv * w4.z; acc[4*j+3] += iv * w4.w;
        }
    }

    float* hp = g_h + (size_t)b * HID * PIX + pix;
    float gs[4] = {0, 0, 0, 0}, gq[4] = {0, 0, 0, 0};
#pragma unroll
    for (int oc = 0; oc < HID; oc++) {
        float v = acc[oc];
        hp[oc * PIX] = v;
        gs[oc >> 3] += v;
        gq[oc >> 3] += v * v;
    }
#pragma unroll
    for (int o = 16; o > 0; o >>= 1) {
#pragma unroll
        for (int g = 0; g < 4; g++) {
            gs[g] += __shfl_down_sync(0xffffffffu, gs[g], o);
            gq[g] += __shfl_down_sync(0xffffffffu, gq[g], o);
        }
    }
    int lane = tid & 31, warp = tid >> 5;
    if (lane == 0) {
#pragma unroll
        for (int g = 0; g < 4; g++) { s_red[warp][g] = gs[g]; s_red[warp][4 + g] = gq[g]; }
    }
    __syncthreads();
    int blin = blockIdx.y * 16 + blockIdx.x;
    if (tid < 8) {
        float v = 0.f;
#pragma unroll
        for (int w = 0; w < 8; w++) v += s_red[w][tid];
        int g = tid & 3, which = tid >> 2;
        g_part[((b * 256 + blin) * 4 + g) * 2 + which] = v;
        __threadfence();
    }
    __syncthreads();
    if (tid == 0) {
        unsigned old = atomicInc(&g_cnt1, NBLK - 1u);
        s_last = (old == NBLK - 1u);
    }
    __syncthreads();
    if (!s_last) return;
    __threadfence();

    // last block: fold GN stats for all 32 (b,g) pairs; 8 lanes per pair
    int pair = tid >> 3, l8 = tid & 7;
    int bb = pair >> 2, g = pair & 3;
    float s = 0.f, q = 0.f;
    for (int i = l8; i < 256; i += 8) {
        s += g_part[((bb * 256 + i) * 4 + g) * 2 + 0];
        q += g_part[((bb * 256 + i) * 4 + g) * 2 + 1];
    }
#pragma unroll
    for (int o = 4; o > 0; o >>= 1) {
        s += __shfl_down_sync(0xffffffffu, s, o, 8);
        q += __shfl_down_sync(0xffffffffu, q, o, 8);
    }
    if (l8 == 0) {
        const float invN = 1.0f / (float)(CPG * PIX);
        float mean = s * invN;
        float Qn = q * invN;
        float var = isinf(Qn) ? Qn : fmaxf(Qn - mean * mean, 0.0f);
        float rstd = rsqrtf(var + EPS);       // var=inf -> rstd=0
#pragma unroll
        for (int c = 0; c < CPG; c++) {
            int gc = g * CPG + c;
            float sc = gn_w[gc] * rstd;
            g_scale[bb * HID + gc] = sc;
            g_shift[bb * HID + gc] = (rstd == 0.0f) ? gn_b[gc] : (gn_b[gc] - mean * sc);
        }
    }
}

// ---------------------------------------------------------------------------
// fused2: GN->GELU->conv2(32->1)->damped update; LAST BLOCK folds diff.
// FILL4 staging + const-offset conv loop + 4 blocks/SM (64-reg cap).
// ---------------------------------------------------------------------------
// fill one pixel (yy,xx) for channels [base, base+4)
#define FILL4(base, yy, xx, inb, hb)                                       \
    {                                                                      \
        float hv[4];                                                       \
        _Pragma("unroll")                                                  \
        for (int c = 0; c < 4; c++)                                        \
            hv[c] = (inb) ? (hb)[(base + c) * PIX] : 0.f;                  \
        _Pragma("unroll")                                                  \
        for (int c = 0; c < 4; c++) {                                      \
            float sc = s_sc[base + c];                                     \
            float t = (sc == 0.0f) ? s_sf[base + c]                        \
                                   : (hv[c] * sc + s_sf[base + c]);        \
            s_h[base + c][yy][xx] = (inb) ? gelu_f(t) : 0.f;               \
        }                                                                  \
    }

__global__ void __launch_bounds__(256, 4) fused2_kernel(
    const float* __restrict__ inp, const float* __restrict__ w2,
    const float* __restrict__ b2, float* __restrict__ final_out, int mode)
{
    if (mode == 0 && g_converged) return;
    const int b = blockIdx.z;
    const int tx0 = blockIdx.x * 16, ty0 = blockIdx.y * 16;
    __shared__ float s_h[HID][18][18];
    __shared__ float s_w[HID * 9];
    __shared__ float s_sc[HID], s_sf[HID];
    __shared__ float s_red[8];
    __shared__ bool s_last;
    int tid = threadIdx.y * 16 + threadIdx.x;

    for (int i = tid; i < HID * 9; i += 256) s_w[i] = w2[i];
    if (tid < HID) { s_sc[tid] = g_scale[b * HID + tid]; s_sf[tid] = g_shift[b * HID + tid]; }
    __syncthreads();

    const float* hp = g_h + (size_t)b * HID * PIX;
    {
        // pixel 1: p = tid (tid < 324 always)
        int yy = tid / 18, xx = tid % 18;
        int gy = ty0 + yy - 1, gx = tx0 + xx - 1;
        bool inb = ((unsigned)gy < 256u) && ((unsigned)gx < 256u);
        const float* hb = hp + (inb ? (gy * WW + gx) : 0);
#pragma unroll
        for (int base = 0; base < HID; base += 4)
            FILL4(base, yy, xx, inb, hb)
        // pixel 2: p = tid + 256 (only tid < 68)
        if (tid < 68) {
            int p2 = tid + 256;
            int yy2 = p2 / 18, xx2 = p2 % 18;
            int gy2 = ty0 + yy2 - 1, gx2 = tx0 + xx2 - 1;
            bool inb2 = ((unsigned)gy2 < 256u) && ((unsigned)gx2 < 256u);
            const float* hb2 = hp + (inb2 ? (gy2 * WW + gx2) : 0);
#pragma unroll
            for (int base = 0; base < HID; base += 4)
                FILL4(base, yy2, xx2, inb2, hb2)
        }
    }
    __syncthreads();

    int ty = threadIdx.y, tx = threadIdx.x;
    // base pointer + all-constant offsets: LDS [Rbase + imm], no per-LDS IMAD
    const float* hb0 = &s_h[0][ty][tx];
    float a0 = 0.f, a1 = 0.f, a2 = 0.f, a3 = 0.f;   // 4 ILP chains over c%4
#pragma unroll
    for (int c = 0; c < HID; c += 4) {
#pragma unroll
        for (int ky = 0; ky < 3; ky++)
#pragma unroll
            for (int kx = 0; kx < 3; kx++) {
                int pos = ky * 3 + kx;
                int ho  = ky * 18 + kx;
                a0 += s_w[(c + 0) * 9 + pos] * hb0[(c + 0) * 324 + ho];
                a1 += s_w[(c + 1) * 9 + pos] * hb0[(c + 1) * 324 + ho];
                a2 += s_w[(c + 2) * 9 + pos] * hb0[(c + 2) * 324 + ho];
                a3 += s_w[(c + 3) * 9 + pos] * hb0[(c + 3) * 324 + ho];
            }
    }
    float acc = b2[0] + ((a0 + a1) + (a2 + a3));

    int pix = (ty0 + ty) * WW + (tx0 + tx);
    int off = b * PIX + pix;
    const float* bp = inp + (size_t)b * 3 * PIX;
    float zold = g_z[off];
    // mirror XLA elementwise rounding exactly (no FMA contraction)
    float ga   = __fmul_rn(g_gamma[b], g_alpha[off]);
    float znew = __fadd_rn(zold, __fmul_rn(ga, acc));
    float m  = bp[PIX + pix];
    float bv = bp[pix];
    float res = __fadd_rn(__fmul_rn(znew, __fadd_rn(1.0f, -m)), __fmul_rn(bv, m));

    if (mode != 0) { final_out[off] = res; return; }

    g_z[off] = res;
    float d = __fadd_rn(res, -zold);
    float s = d * d;
#pragma unroll
    for (int o = 16; o > 0; o >>= 1) s += __shfl_down_sync(0xffffffffu, s, o);
    int lane = tid & 31, warp = tid >> 5;
    if (lane == 0) s_red[warp] = s;
    __syncthreads();
    int blin = blockIdx.y * 16 + blockIdx.x;
    if (tid == 0) {
        float t = 0.f;
#pragma unroll
        for (int w = 0; w < 8; w++) t += s_red[w];
        g_diffpart[b * 256 + blin] = t;
        __threadfence();
        unsigned old = atomicInc(&g_cnt2, NBLK - 1u);
        s_last = (old == NBLK - 1u);
    }
    __syncthreads();
    if (!s_last) return;
    __threadfence();

    // last block: diff = mean_b ||dz_b||; jax cond continues while diff>=TOL
    int w = tid >> 5, l = tid & 31;
    float t = 0.f;
    for (int i = l; i < 256; i += 32) t += g_diffpart[w * 256 + i];
#pragma unroll
    for (int o = 16; o > 0; o >>= 1) t += __shfl_down_sync(0xffffffffu, t, o);
    __shared__ float sb[8];
    if (l == 0) sb[w] = sqrtf(t);
    __syncthreads();
    if (tid == 0) {
        float mm = 0.f;
#pragma unroll
        for (int bb = 0; bb < 8; bb++) mm += sb[bb];
        mm *= 0.125f;
        if (!(mm >= TOL)) g_converged = 1;   // NaN also stops (matches jax)
    }
}

// ---------------------------------------------------------------------------
extern "C" void kernel_launch(void* const* d_in, const int* in_sizes, int n_in,
                              void* d_out, int out_size)
{
    const float* inp     = (const float*)d_in[0];
    const float* core_w1 = (const float*)d_in[1];
    const float* core_b1 = (const float*)d_in[2];
    const float* gn_w    = (const float*)d_in[3];
    const float* gn_b    = (const float*)d_in[4];
    const float* core_w2 = (const float*)d_in[5];
    const float* core_b2 = (const float*)d_in[6];
    const float* stab_w1 = (const float*)d_in[7];
    const float* stab_b1 = (const float*)d_in[8];
    const float* stab_w2 = (const float*)d_in[9];
    const float* stab_b2 = (const float*)d_in[10];
    const float* fc1_w   = (const float*)d_in[11];
    const float* fc1_b   = (const float*)d_in[12];
    const float* fc2_w   = (const float*)d_in[13];
    const float* fc2_b   = (const float*)d_in[14];
    float* out = (float*)d_out;

    dim3 blk(16, 16);
    dim3 grd(16, 16, BATCH);

    // fused2 is the 4th launch (ncu capture window)
    stab1_kernel<<<grd, blk>>>(inp, stab_w1, stab_b1, fc1_w, fc1_b, fc2_w, fc2_b);
    prep_kernel<<<grd, blk>>>(inp, stab_w2, stab_b2, core_w1, core_b1);
    convz_kernel<<<grd, blk>>>(core_w1, gn_w, gn_b, 1);
    fused2_kernel<<<grd, blk>>>(inp, core_w2, core_b2, nullptr, 0);

    for (int it = 1; it < MAX_ITER; ++it) {
        convz_kernel<<<grd, blk>>>(core_w1, gn_w, gn_b, 1);
        fused2_kernel<<<grd, blk>>>(inp, core_w2, core_b2, nullptr, 0);
    }
    // final core_f (always runs): z_star -> d_out
    convz_kernel<<<grd, blk>>>(core_w1, gn_w, gn_b, 0);
    fused2_kernel<<<grd, blk>>>(inp, core_w2, core_b2, out, 1);
}

// round 11
// speedup vs baseline: 1.2594x; 1.2594x over previous
#include <cuda_runtime.h>
#include <cuda_bf16.h>
#include <math.h>

// ---------------------------------------------------------------------------
// MultiDEQPDEBlock: DEQ fixed-point PDE solver  (B=8, 256x256, hid=32, GN4)
// core_f: conv3x3(4->32) -> GN(4) -> GELU(erf) -> conv3x3(32->1) -> damped update
// h_fixed (conv of loop-invariant [b,m,k]) precomputed once; per-iter conv1 is
// the 9-tap z convolution. fused2 normal path = r9 optimum (FILL8, occ~35%).
// FAST PATH: once ALL GN groups of a batch overflow (sc==0 for all 32 ch),
// G = gelu(gn_b) is spatially constant -> dz is a tap-mask-weighted constant;
// staging+conv skipped entirely (late ~29 of 51 iterations).
// Divergent dynamics (|1-mask|>1) -> ~1e37; overflow paths mirror jax
// (var->inf, rstd->0, xn->0; NaN diff stops loop).
// ---------------------------------------------------------------------------

#define BATCH 8
#define HH 256
#define WW 256
#define PIX (HH*WW)
#define HID 32
#define SHID 16
#define GROUPS 4
#define CPG 8
#define EPS 1e-5f
#define TOL 1e-4f
#define MAX_ITER 50
#define CFL_SCALE 0.015625f
#define NBLK 2048               // (16,16,8) grids

// ---- scratch (device globals; no cudaMalloc allowed) ----
__device__ float g_h[(size_t)BATCH*HID*PIX];      // 64 MB conv1 output (pre-GN)
__device__ float g_hfix[(size_t)BATCH*HID*PIX];   // 64 MB conv of fixed channels
__device__ float g_sh[(size_t)BATCH*SHID*PIX];    // 32 MB stabilizer hidden
__device__ float g_alpha[(size_t)BATCH*PIX];
__device__ float g_z[(size_t)BATCH*PIX];
__device__ float g_gamma[BATCH];
__device__ float g_part[BATCH*256*GROUPS*2];
__device__ float g_spart[BATCH*256*4];
__device__ float g_scale[BATCH*HID];
__device__ float g_shift[BATCH*HID];
__device__ float g_diffpart[BATCH*256];
__device__ int   g_converged;
__device__ unsigned g_cnt0;     // zero-init; self-resetting via atomicInc wrap
__device__ unsigned g_cnt1;
__device__ unsigned g_cnt2;

__device__ __forceinline__ float gelu_f(float x) {
    return 0.5f * x * (1.0f + erff(x * 0.70710678118654752f));
}
__device__ __forceinline__ float sigmoid_f(float x) {
    return 1.0f / (1.0f + expf(-x));
}

// ---------------------------------------------------------------------------
// stabilizer conv1 (3->16, GELU) + z init + spec partials; last block: gamma MLP
// ---------------------------------------------------------------------------
__global__ void __launch_bounds__(256) stab1_kernel(
    const float* __restrict__ inp, const float* __restrict__ w,
    const float* __restrict__ bias,
    const float* __restrict__ fc1_w, const float* __restrict__ fc1_b,
    const float* __restrict__ fc2_w, const float* __restrict__ fc2_b)
{
    const int b = blockIdx.z;
    const int tx0 = blockIdx.x * 16, ty0 = blockIdx.y * 16;
    __shared__ float s_in[3][18][18];
    __shared__ float s_w[27][16];
    __shared__ float s_b[16];
    __shared__ float s_red[8][4];
    __shared__ bool s_last;
    int tid = threadIdx.y * 16 + threadIdx.x;

    if (tid == 0 && blockIdx.x == 0 && blockIdx.y == 0 && b == 0) g_converged = 0;

    for (int i = tid; i < SHID * 27; i += 256) {
        int oc = i / 27, r = i % 27;
        s_w[r][oc] = w[i];
    }
    if (tid < SHID) s_b[tid] = bias[tid];

    const float* bp = inp + (size_t)b * 3 * PIX;
    for (int i = tid; i < 3 * 324; i += 256) {
        int c = i / 324, r = i % 324, yy = r / 18, xx = r % 18;
        int gy = ty0 + yy - 1, gx = tx0 + xx - 1;
        float v = 0.f;
        if ((unsigned)gy < 256u && (unsigned)gx < 256u)
            v = bp[c * PIX + gy * WW + gx];
        s_in[c][yy][xx] = v;
    }
    __syncthreads();

    int ty = threadIdx.y, tx = threadIdx.x;
    float in[27];
#pragma unroll
    for (int c = 0; c < 3; c++)
#pragma unroll
        for (int ky = 0; ky < 3; ky++)
#pragma unroll
            for (int kx = 0; kx < 3; kx++)
                in[c * 9 + ky * 3 + kx] = s_in[c][ty + ky][tx + kx];

    float acc[SHID];
#pragma unroll
    for (int oc = 0; oc < SHID; oc++) acc[oc] = s_b[oc];
#pragma unroll
    for (int r = 0; r < 27; r++) {
        float iv = in[r];
#pragma unroll
        for (int oc = 0; oc < SHID; oc++) acc[oc] += iv * s_w[r][oc];
    }

    int pix = (ty0 + ty) * WW + (tx0 + tx);
    float* out = g_sh + (size_t)b * SHID * PIX + pix;
#pragma unroll
    for (int oc = 0; oc < SHID; oc++)
        out[oc * PIX] = gelu_f(acc[oc]);

    // z init (channel 0 = boundary)
    g_z[b * PIX + pix] = s_in[0][ty + 1][tx + 1];

    // spec partials: |boundary| and k stats
    float bv = fabsf(s_in[0][ty + 1][tx + 1]);
    float kv = s_in[2][ty + 1][tx + 1];
    float s1 = bv, q1 = bv * bv, s2 = kv, q2 = kv * kv;
#pragma unroll
    for (int o = 16; o > 0; o >>= 1) {
        s1 += __shfl_down_sync(0xffffffffu, s1, o);
        q1 += __shfl_down_sync(0xffffffffu, q1, o);
        s2 += __shfl_down_sync(0xffffffffu, s2, o);
        q2 += __shfl_down_sync(0xffffffffu, q2, o);
    }
    int lane = tid & 31, warp = tid >> 5;
    if (lane == 0) { s_red[warp][0] = s1; s_red[warp][1] = q1; s_red[warp][2] = s2; s_red[warp][3] = q2; }
    __syncthreads();
    int blin = blockIdx.y * 16 + blockIdx.x;
    if (tid < 4) {
        float v = 0.f;
#pragma unroll
        for (int w8 = 0; w8 < 8; w8++) v += s_red[w8][tid];
        g_spart[(b * 256 + blin) * 4 + tid] = v;
        __threadfence();
    }
    __syncthreads();
    if (tid == 0) {
        unsigned old = atomicInc(&g_cnt0, NBLK - 1u);
        s_last = (old == NBLK - 1u);
    }
    __syncthreads();
    if (!s_last) return;
    __threadfence();

    // last block: per-batch spec_ctrl MLP -> gamma (warp w = batch w)
    int w8 = tid >> 5, l = tid & 31;
    float S1 = 0, Q1 = 0, S2 = 0, Q2 = 0;
    for (int i = l; i < 256; i += 32) {
        S1 += g_spart[(w8 * 256 + i) * 4 + 0];
        Q1 += g_spart[(w8 * 256 + i) * 4 + 1];
        S2 += g_spart[(w8 * 256 + i) * 4 + 2];
        Q2 += g_spart[(w8 * 256 + i) * 4 + 3];
    }
#pragma unroll
    for (int o = 16; o > 0; o >>= 1) {
        S1 += __shfl_down_sync(0xffffffffu, S1, o);
        Q1 += __shfl_down_sync(0xffffffffu, Q1, o);
        S2 += __shfl_down_sync(0xffffffffu, S2, o);
        Q2 += __shfl_down_sync(0xffffffffu, Q2, o);
    }
    if (l == 0) {
        const float N = (float)PIX;
        float m1 = S1 / N, m2 = S2 / N;
        float v1 = (Q1 - N * m1 * m1) / (N - 1.0f);
        float v2 = (Q2 - N * m2 * m2) / (N - 1.0f);
        float feat[5] = { m1, sqrtf(fmaxf(v1, 0.f)), m2, sqrtf(fmaxf(v2, 0.f)), 1.0f };
        float outv = fc2_b[0];
        for (int j = 0; j < 32; j++) {
            float t = fc1_b[j];
#pragma unroll
            for (int i = 0; i < 5; i++) t += feat[i] * fc1_w[j * 5 + i];
            outv += gelu_f(t) * fc2_w[j];
        }
        g_gamma[w8] = (0.5f + 1.5f * sigmoid_f(outv)) * CFL_SCALE;
    }
}

// ---------------------------------------------------------------------------
// prep: stab2 (16->1 sigmoid -> alpha)  AND  hfix (conv3x3 of [b,m,k] + bias)
// ---------------------------------------------------------------------------
__global__ void __launch_bounds__(256) prep_kernel(
    const float* __restrict__ inp,
    const float* __restrict__ w2s, const float* __restrict__ b2s,
    const float* __restrict__ w1, const float* __restrict__ b1)
{
    const int b = blockIdx.z;
    const int tx0 = blockIdx.x * 16, ty0 = blockIdx.y * 16;
    __shared__ float s_sh[SHID][18][18];
    __shared__ float s_in[3][18][18];
    __shared__ float s_ws[SHID * 9];
    __shared__ __align__(16) float s_wh[27][32];
    __shared__ float s_bh[32];
    int tid = threadIdx.y * 16 + threadIdx.x;

    if (tid < SHID * 9) s_ws[tid] = w2s[tid];
    for (int i = tid; i < HID * 27; i += 256) {
        int oc = i / 27, r = i % 27;
        s_wh[r][oc] = w1[oc * 36 + 9 + r];   // skip z-channel taps
    }
    if (tid < HID) s_bh[tid] = b1[tid];

    const float* hp = g_sh + (size_t)b * SHID * PIX;
    for (int i = tid; i < SHID * 324; i += 256) {
        int c = i / 324, r = i % 324, yy = r / 18, xx = r % 18;
        int gy = ty0 + yy - 1, gx = tx0 + xx - 1;
        float v = 0.f;
        if ((unsigned)gy < 256u && (unsigned)gx < 256u)
            v = hp[c * PIX + gy * WW + gx];
        s_sh[c][yy][xx] = v;
    }
    const float* bp = inp + (size_t)b * 3 * PIX;
    for (int i = tid; i < 3 * 324; i += 256) {
        int c = i / 324, r = i % 324, yy = r / 18, xx = r % 18;
        int gy = ty0 + yy - 1, gx = tx0 + xx - 1;
        float v = 0.f;
        if ((unsigned)gy < 256u && (unsigned)gx < 256u)
            v = bp[c * PIX + gy * WW + gx];
        s_in[c][yy][xx] = v;
    }
    __syncthreads();

    int ty = threadIdx.y, tx = threadIdx.x;
    int pix = (ty0 + ty) * WW + (tx0 + tx);

    // stab2: alpha
    {
        float acc = b2s[0];
#pragma unroll
        for (int c = 0; c < SHID; c++)
#pragma unroll
            for (int ky = 0; ky < 3; ky++)
#pragma unroll
                for (int kx = 0; kx < 3; kx++)
                    acc += s_ws[c * 9 + ky * 3 + kx] * s_sh[c][ty + ky][tx + kx];
        g_alpha[(size_t)b * PIX + pix] = sigmoid_f(acc);
    }

    // hfix: 27-tap conv of fixed channels into 32 outputs
    {
        float acc[HID];
#pragma unroll
        for (int oc = 0; oc < HID; oc++) acc[oc] = s_bh[oc];
#pragma unroll
        for (int c = 0; c < 3; c++)
#pragma unroll
            for (int ky = 0; ky < 3; ky++)
#pragma unroll
                for (int kx = 0; kx < 3; kx++) {
                    float iv = s_in[c][ty + ky][tx + kx];
                    int r = c * 9 + ky * 3 + kx;
#pragma unroll
                    for (int j = 0; j < 8; j++) {
                        float4 w4 = ((const float4*)&s_wh[r][0])[j];
                        acc[4*j+0] += iv * w4.x; acc[4*j+1] += iv * w4.y;
                        acc[4*j+2] += iv * w4.z; acc[4*j+3] += iv * w4.w;
                    }
                }
        float* op = g_hfix + (size_t)b * HID * PIX + pix;
#pragma unroll
        for (int oc = 0; oc < HID; oc++) op[oc * PIX] = acc[oc];
    }
}

// ---------------------------------------------------------------------------
// convz: h = h_fixed + conv3x3(z, w1[:,0])  (9 taps), write g_h + GN partials;
// LAST BLOCK folds GN stats -> scale/shift.
// ---------------------------------------------------------------------------
__global__ void __launch_bounds__(256, 4) convz_kernel(
    const float* __restrict__ w1, const float* __restrict__ gn_w,
    const float* __restrict__ gn_b, int check)
{
    if (check && g_converged) return;
    const int b = blockIdx.z;
    const int tx0 = blockIdx.x * 16, ty0 = blockIdx.y * 16;
    __shared__ float s_z[18][18];
    __shared__ __align__(16) float s_w[9][32];
    __shared__ float s_red[8][8];
    __shared__ bool s_last;
    int tid = threadIdx.y * 16 + threadIdx.x;

    for (int i = tid; i < HID * 9; i += 256) {
        int oc = i / 9, r = i % 9;
        s_w[r][oc] = w1[oc * 36 + r];       // z-channel taps (c=0)
    }

    const float* zp = g_z + b * PIX;
    for (int i = tid; i < 324; i += 256) {
        int yy = i / 18, xx = i % 18;
        int gy = ty0 + yy - 1, gx = tx0 + xx - 1;
        float v = 0.f;
        if ((unsigned)gy < 256u && (unsigned)gx < 256u)
            v = zp[gy * WW + gx];
        s_z[yy][xx] = v;
    }
    __syncthreads();

    int ty = threadIdx.y, tx = threadIdx.x;
    float zv[9];
#pragma unroll
    for (int ky = 0; ky < 3; ky++)
#pragma unroll
        for (int kx = 0; kx < 3; kx++)
            zv[ky * 3 + kx] = s_z[ty + ky][tx + kx];

    int pix = (ty0 + ty) * WW + (tx0 + tx);
    const float* fp = g_hfix + (size_t)b * HID * PIX + pix;
    float acc[HID];
#pragma unroll
    for (int oc = 0; oc < HID; oc++) acc[oc] = fp[oc * PIX];
#pragma unroll
    for (int r = 0; r < 9; r++) {
        float iv = zv[r];
#pragma unroll
        for (int j = 0; j < 8; j++) {
            float4 w4 = ((const float4*)&s_w[r][0])[j];
            acc[4*j+0] += iv * w4.x; acc[4*j+1] += iv * w4.y;
            acc[4*j+2] += iv * w4.z; acc[4*j+3] += iv * w4.w;
        }
    }

    float* hp = g_h + (size_t)b * HID * PIX + pix;
    float gs[4] = {0, 0, 0, 0}, gq[4] = {0, 0, 0, 0};
#pragma unroll
    for (int oc = 0; oc < HID; oc++) {
        float v = acc[oc];
        hp[oc * PIX] = v;
        gs[oc >> 3] += v;
        gq[oc >> 3] += v * v;
    }
#pragma unroll
    for (int o = 16; o > 0; o >>= 1) {
#pragma unroll
        for (int g = 0; g < 4; g++) {
            gs[g] += __shfl_down_sync(0xffffffffu, gs[g], o);
            gq[g] += __shfl_down_sync(0xffffffffu, gq[g], o);
        }
    }
    int lane = tid & 31, warp = tid >> 5;
    if (lane == 0) {
#pragma unroll
        for (int g = 0; g < 4; g++) { s_red[warp][g] = gs[g]; s_red[warp][4 + g] = gq[g]; }
    }
    __syncthreads();
    int blin = blockIdx.y * 16 + blockIdx.x;
    if (tid < 8) {
        float v = 0.f;
#pragma unroll
        for (int w = 0; w < 8; w++) v += s_red[w][tid];
        int g = tid & 3, which = tid >> 2;
        g_part[((b * 256 + blin) * 4 + g) * 2 + which] = v;
        __threadfence();
    }
    __syncthreads();
    if (tid == 0) {
        unsigned old = atomicInc(&g_cnt1, NBLK - 1u);
        s_last = (old == NBLK - 1u);
    }
    __syncthreads();
    if (!s_last) return;
    __threadfence();

    // last block: fold GN stats for all 32 (b,g) pairs; 8 lanes per pair
    int pair = tid >> 3, l8 = tid & 7;
    int bb = pair >> 2, g = pair & 3;
    float s = 0.f, q = 0.f;
    for (int i = l8; i < 256; i += 8) {
        s += g_part[((bb * 256 + i) * 4 + g) * 2 + 0];
        q += g_part[((bb * 256 + i) * 4 + g) * 2 + 1];
    }
#pragma unroll
    for (int o = 4; o > 0; o >>= 1) {
        s += __shfl_down_sync(0xffffffffu, s, o, 8);
        q += __shfl_down_sync(0xffffffffu, q, o, 8);
    }
    if (l8 == 0) {
        const float invN = 1.0f / (float)(CPG * PIX);
        float mean = s * invN;
        float Qn = q * invN;
        float var = isinf(Qn) ? Qn : fmaxf(Qn - mean * mean, 0.0f);
        float rstd = rsqrtf(var + EPS);       // var=inf -> rstd=0
#pragma unroll
        for (int c = 0; c < CPG; c++) {
            int gc = g * CPG + c;
            float sc = gn_w[gc] * rstd;
            g_scale[bb * HID + gc] = sc;
            g_shift[bb * HID + gc] = (rstd == 0.0f) ? gn_b[gc] : (gn_b[gc] - mean * sc);
        }
    }
}

// ---------------------------------------------------------------------------
// fused2: GN->GELU->conv2(32->1)->damped update; LAST BLOCK folds diff.
// Normal path = r9 optimum (FILL8, occ~35%). FAST path: all sc==0 for this
// batch -> G=gelu(gn_b) constant -> dz = b2 + sum_c G_c * (valid-tap wsum).
// ---------------------------------------------------------------------------
// fill one pixel (yy,xx) for channels [base, base+8)
#define FILL8(base, yy, xx, inb, hb)                                       \
    {                                                                      \
        float hv[8];                                                       \
        _Pragma("unroll")                                                  \
        for (int c = 0; c < 8; c++)                                        \
            hv[c] = (inb) ? (hb)[(base + c) * PIX] : 0.f;                  \
        _Pragma("unroll")                                                  \
        for (int c = 0; c < 8; c++) {                                      \
            float sc = s_sc[base + c];                                     \
            float t = (sc == 0.0f) ? s_sf[base + c]                        \
                                   : (hv[c] * sc + s_sf[base + c]);        \
            s_h[base + c][yy][xx] = (inb) ? gelu_f(t) : 0.f;               \
        }                                                                  \
    }

__global__ void __launch_bounds__(256, 3) fused2_kernel(
    const float* __restrict__ inp, const float* __restrict__ w2,
    const float* __restrict__ b2, float* __restrict__ final_out, int mode)
{
    if (mode == 0 && g_converged) return;
    const int b = blockIdx.z;
    const int tx0 = blockIdx.x * 16, ty0 = blockIdx.y * 16;
    __shared__ float s_h[HID][18][18];
    __shared__ float s_w[HID * 9];
    __shared__ float s_sc[HID], s_sf[HID];
    __shared__ float s_G[HID];
    __shared__ float s_red[8];
    __shared__ float s_Dfull;
    __shared__ bool s_fast;
    __shared__ bool s_last;
    int tid = threadIdx.y * 16 + threadIdx.x;

    for (int i = tid; i < HID * 9; i += 256) s_w[i] = w2[i];
    if (tid < HID) { s_sc[tid] = g_scale[b * HID + tid]; s_sf[tid] = g_shift[b * HID + tid]; }
    __syncthreads();

    // warp 0: overflow fast-path detection + constant-G precompute
    if (tid < 32) {
        int zero = (s_sc[tid] == 0.0f);
        unsigned bal = __ballot_sync(0xffffffffu, zero);
        float wsum = 0.f;
#pragma unroll
        for (int j = 0; j < 9; j++) wsum += s_w[tid * 9 + j];
        float Gc = gelu_f(s_sf[tid]);     // == gelu(gn_b) when sc==0
        s_G[tid] = Gc;
        float t = Gc * wsum;
#pragma unroll
        for (int o = 16; o > 0; o >>= 1) t += __shfl_down_sync(0xffffffffu, t, o);
        if (tid == 0) { s_fast = (bal == 0xffffffffu); s_Dfull = t; }
    }
    __syncthreads();

    int ty = threadIdx.y, tx = threadIdx.x;
    float acc;

    if (s_fast) {
        // all sc==0: G constant per channel; dz depends only on valid-tap mask
        int Y = ty0 + ty, X = tx0 + tx;
        bool interior = (Y >= 1) && (Y <= 254) && (X >= 1) && (X <= 254);
        if (interior) {
            acc = b2[0] + s_Dfull;
        } else {
            acc = b2[0];
            int ky0 = (Y == 0) ? 1 : 0, ky1 = (Y == 255) ? 2 : 3;
            int kx0 = (X == 0) ? 1 : 0, kx1 = (X == 255) ? 2 : 3;
            for (int c = 0; c < HID; c++) {
                float wsum = 0.f;
                for (int ky = ky0; ky < ky1; ky++)
                    for (int kx = kx0; kx < kx1; kx++)
                        wsum += s_w[c * 9 + ky * 3 + kx];
                acc += s_G[c] * wsum;
            }
        }
    } else {
        const float* hp = g_h + (size_t)b * HID * PIX;
        {
            // pixel 1: p = tid (tid < 324 always)
            int yy = tid / 18, xx = tid % 18;
            int gy = ty0 + yy - 1, gx = tx0 + xx - 1;
            bool inb = ((unsigned)gy < 256u) && ((unsigned)gx < 256u);
            const float* hb = hp + (inb ? (gy * WW + gx) : 0);
            FILL8(0, yy, xx, inb, hb)
            FILL8(8, yy, xx, inb, hb)
            FILL8(16, yy, xx, inb, hb)
            FILL8(24, yy, xx, inb, hb)
            // pixel 2: p = tid + 256 (only tid < 68)
            if (tid < 68) {
                int p2 = tid + 256;
                int yy2 = p2 / 18, xx2 = p2 % 18;
                int gy2 = ty0 + yy2 - 1, gx2 = tx0 + xx2 - 1;
                bool inb2 = ((unsigned)gy2 < 256u) && ((unsigned)gx2 < 256u);
                const float* hb2 = hp + (inb2 ? (gy2 * WW + gx2) : 0);
                FILL8(0, yy2, xx2, inb2, hb2)
                FILL8(8, yy2, xx2, inb2, hb2)
                FILL8(16, yy2, xx2, inb2, hb2)
                FILL8(24, yy2, xx2, inb2, hb2)
            }
        }
        __syncthreads();

        float a0 = 0.f, a1 = 0.f, a2 = 0.f, a3 = 0.f;   // 4 ILP chains over c%4
#pragma unroll
        for (int c = 0; c < HID; c += 4) {
#pragma unroll
            for (int ky = 0; ky < 3; ky++)
#pragma unroll
                for (int kx = 0; kx < 3; kx++) {
                    int pos = ky * 3 + kx;
                    a0 += s_w[(c + 0) * 9 + pos] * s_h[c + 0][ty + ky][tx + kx];
                    a1 += s_w[(c + 1) * 9 + pos] * s_h[c + 1][ty + ky][tx + kx];
                    a2 += s_w[(c + 2) * 9 + pos] * s_h[c + 2][ty + ky][tx + kx];
                    a3 += s_w[(c + 3) * 9 + pos] * s_h[c + 3][ty + ky][tx + kx];
                }
        }
        acc = b2[0] + ((a0 + a1) + (a2 + a3));
    }

    int pix = (ty0 + ty) * WW + (tx0 + tx);
    int off = b * PIX + pix;
    const float* bp = inp + (size_t)b * 3 * PIX;
    float zold = g_z[off];
    // mirror XLA elementwise rounding exactly (no FMA contraction)
    float ga   = __fmul_rn(g_gamma[b], g_alpha[off]);
    float znew = __fadd_rn(zold, __fmul_rn(ga, acc));
    float m  = bp[PIX + pix];
    float bv = bp[pix];
    float res = __fadd_rn(__fmul_rn(znew, __fadd_rn(1.0f, -m)), __fmul_rn(bv, m));

    if (mode != 0) { final_out[off] = res; return; }

    g_z[off] = res;
    float d = __fadd_rn(res, -zold);
    float s = d * d;
#pragma unroll
    for (int o = 16; o > 0; o >>= 1) s += __shfl_down_sync(0xffffffffu, s, o);
    int lane = tid & 31, warp = tid >> 5;
    if (lane == 0) s_red[warp] = s;
    __syncthreads();
    int blin = blockIdx.y * 16 + blockIdx.x;
    if (tid == 0) {
        float t = 0.f;
#pragma unroll
        for (int w = 0; w < 8; w++) t += s_red[w];
        g_diffpart[b * 256 + blin] = t;
        __threadfence();
        unsigned old = atomicInc(&g_cnt2, NBLK - 1u);
        s_last = (old == NBLK - 1u);
    }
    __syncthreads();
    if (!s_last) return;
    __threadfence();

    // last block: diff = mean_b ||dz_b||; jax cond continues while diff>=TOL
    int w = tid >> 5, l = tid & 31;
    float t = 0.f;
    for (int i = l; i < 256; i += 32) t += g_diffpart[w * 256 + i];
#pragma unroll
    for (int o = 16; o > 0; o >>= 1) t += __shfl_down_sync(0xffffffffu, t, o);
    __shared__ float sb[8];
    if (l == 0) sb[w] = sqrtf(t);
    __syncthreads();
    if (tid == 0) {
        float mm = 0.f;
#pragma unroll
        for (int bb = 0; bb < 8; bb++) mm += sb[bb];
        mm *= 0.125f;
        if (!(mm >= TOL)) g_converged = 1;   // NaN also stops (matches jax)
    }
}

// ---------------------------------------------------------------------------
extern "C" void kernel_launch(void* const* d_in, const int* in_sizes, int n_in,
                              void* d_out, int out_size)
{
    const float* inp     = (const float*)d_in[0];
    const float* core_w1 = (const float*)d_in[1];
    const float* core_b1 = (const float*)d_in[2];
    const float* gn_w    = (const float*)d_in[3];
    const float* gn_b    = (const float*)d_in[4];
    const float* core_w2 = (const float*)d_in[5];
    const float* core_b2 = (const float*)d_in[6];
    const float* stab_w1 = (const float*)d_in[7];
    const float* stab_b1 = (const float*)d_in[8];
    const float* stab_w2 = (const float*)d_in[9];
    const float* stab_b2 = (const float*)d_in[10];
    const float* fc1_w   = (const float*)d_in[11];
    const float* fc1_b   = (const float*)d_in[12];
    const float* fc2_w   = (const float*)d_in[13];
    const float* fc2_b   = (const float*)d_in[14];
    float* out = (float*)d_out;

    dim3 blk(16, 16);
    dim3 grd(16, 16, BATCH);

    // fused2 is the 4th launch (ncu capture window; iter-1 normal path)
    stab1_kernel<<<grd, blk>>>(inp, stab_w1, stab_b1, fc1_w, fc1_b, fc2_w, fc2_b);
    prep_kernel<<<grd, blk>>>(inp, stab_w2, stab_b2, core_w1, core_b1);
    convz_kernel<<<grd, blk>>>(core_w1, gn_w, gn_b, 1);
    fused2_kernel<<<grd, blk>>>(inp, core_w2, core_b2, nullptr, 0);

    for (int it = 1; it < MAX_ITER; ++it) {
        convz_kernel<<<grd, blk>>>(core_w1, gn_w, gn_b, 1);
        fused2_kernel<<<grd, blk>>>(inp, core_w2, core_b2, nullptr, 0);
    }
    // final core_f (always runs): z_star -> d_out
    convz_kernel<<<grd, blk>>>(core_w1, gn_w, gn_b, 0);
    fused2_kernel<<<grd, blk>>>(inp, core_w2, core_b2, out, 1);
}

// round 12
// speedup vs baseline: 1.3801x; 1.0958x over previous
#include <cuda_runtime.h>
#include <cuda_bf16.h>
#include <math.h>

// ---------------------------------------------------------------------------
// MultiDEQPDEBlock: DEQ fixed-point PDE solver  (B=8, 256x256, hid=32, GN4)
// core_f: conv3x3(4->32) -> GN(4) -> GELU(erf) -> conv3x3(32->1) -> damped update
// h_fixed (conv of loop-invariant [b,m,k]) precomputed once; per-iter conv1 is
// the 9-tap z convolution. fused2 tile reshaped to 32x8 (warp = one 32-wide
// row) -> conflict-free LDS in the conv loop. FAST PATH (all GN groups of a
// batch overflowed): G=gelu(gn_b) constant -> dz = tap-mask-weighted constant.
// Divergent dynamics (|1-mask|>1) -> ~1e37; overflow paths mirror jax
// (var->inf, rstd->0, xn->0; NaN diff stops loop).
// ---------------------------------------------------------------------------

#define BATCH 8
#define HH 256
#define WW 256
#define PIX (HH*WW)
#define HID 32
#define SHID 16
#define GROUPS 4
#define CPG 8
#define EPS 1e-5f
#define TOL 1e-4f
#define MAX_ITER 50
#define CFL_SCALE 0.015625f
#define NBLK 2048               // 2048 blocks in iter-kernels' grids

// ---- scratch (device globals; no cudaMalloc allowed) ----
__device__ float g_h[(size_t)BATCH*HID*PIX];      // 64 MB conv1 output (pre-GN)
__device__ float g_hfix[(size_t)BATCH*HID*PIX];   // 64 MB conv of fixed channels
__device__ float g_sh[(size_t)BATCH*SHID*PIX];    // 32 MB stabilizer hidden
__device__ float g_alpha[(size_t)BATCH*PIX];
__device__ float g_z[(size_t)BATCH*PIX];
__device__ float g_gamma[BATCH];
__device__ float g_part[BATCH*256*GROUPS*2];
__device__ float g_spart[BATCH*256*4];
__device__ float g_scale[BATCH*HID];
__device__ float g_shift[BATCH*HID];
__device__ float g_diffpart[BATCH*256];
__device__ int   g_converged;
__device__ unsigned g_cnt0;     // zero-init; self-resetting via atomicInc wrap
__device__ unsigned g_cnt1;
__device__ unsigned g_cnt2;

__device__ __forceinline__ float gelu_f(float x) {
    return 0.5f * x * (1.0f + erff(x * 0.70710678118654752f));
}
__device__ __forceinline__ float sigmoid_f(float x) {
    return 1.0f / (1.0f + expf(-x));
}

// ---------------------------------------------------------------------------
// stabilizer conv1 (3->16, GELU) + z init + spec partials; last block: gamma MLP
// ---------------------------------------------------------------------------
__global__ void __launch_bounds__(256) stab1_kernel(
    const float* __restrict__ inp, const float* __restrict__ w,
    const float* __restrict__ bias,
    const float* __restrict__ fc1_w, const float* __restrict__ fc1_b,
    const float* __restrict__ fc2_w, const float* __restrict__ fc2_b)
{
    const int b = blockIdx.z;
    const int tx0 = blockIdx.x * 16, ty0 = blockIdx.y * 16;
    __shared__ float s_in[3][18][18];
    __shared__ float s_w[27][16];
    __shared__ float s_b[16];
    __shared__ float s_red[8][4];
    __shared__ bool s_last;
    int tid = threadIdx.y * 16 + threadIdx.x;

    if (tid == 0 && blockIdx.x == 0 && blockIdx.y == 0 && b == 0) g_converged = 0;

    for (int i = tid; i < SHID * 27; i += 256) {
        int oc = i / 27, r = i % 27;
        s_w[r][oc] = w[i];
    }
    if (tid < SHID) s_b[tid] = bias[tid];

    const float* bp = inp + (size_t)b * 3 * PIX;
    for (int i = tid; i < 3 * 324; i += 256) {
        int c = i / 324, r = i % 324, yy = r / 18, xx = r % 18;
        int gy = ty0 + yy - 1, gx = tx0 + xx - 1;
        float v = 0.f;
        if ((unsigned)gy < 256u && (unsigned)gx < 256u)
            v = bp[c * PIX + gy * WW + gx];
        s_in[c][yy][xx] = v;
    }
    __syncthreads();

    int ty = threadIdx.y, tx = threadIdx.x;
    float in[27];
#pragma unroll
    for (int c = 0; c < 3; c++)
#pragma unroll
        for (int ky = 0; ky < 3; ky++)
#pragma unroll
            for (int kx = 0; kx < 3; kx++)
                in[c * 9 + ky * 3 + kx] = s_in[c][ty + ky][tx + kx];

    float acc[SHID];
#pragma unroll
    for (int oc = 0; oc < SHID; oc++) acc[oc] = s_b[oc];
#pragma unroll
    for (int r = 0; r < 27; r++) {
        float iv = in[r];
#pragma unroll
        for (int oc = 0; oc < SHID; oc++) acc[oc] += iv * s_w[r][oc];
    }

    int pix = (ty0 + ty) * WW + (tx0 + tx);
    float* out = g_sh + (size_t)b * SHID * PIX + pix;
#pragma unroll
    for (int oc = 0; oc < SHID; oc++)
        out[oc * PIX] = gelu_f(acc[oc]);

    // z init (channel 0 = boundary)
    g_z[b * PIX + pix] = s_in[0][ty + 1][tx + 1];

    // spec partials: |boundary| and k stats
    float bv = fabsf(s_in[0][ty + 1][tx + 1]);
    float kv = s_in[2][ty + 1][tx + 1];
    float s1 = bv, q1 = bv * bv, s2 = kv, q2 = kv * kv;
#pragma unroll
    for (int o = 16; o > 0; o >>= 1) {
        s1 += __shfl_down_sync(0xffffffffu, s1, o);
        q1 += __shfl_down_sync(0xffffffffu, q1, o);
        s2 += __shfl_down_sync(0xffffffffu, s2, o);
        q2 += __shfl_down_sync(0xffffffffu, q2, o);
    }
    int lane = tid & 31, warp = tid >> 5;
    if (lane == 0) { s_red[warp][0] = s1; s_red[warp][1] = q1; s_red[warp][2] = s2; s_red[warp][3] = q2; }
    __syncthreads();
    int blin = blockIdx.y * 16 + blockIdx.x;
    if (tid < 4) {
        float v = 0.f;
#pragma unroll
        for (int w8 = 0; w8 < 8; w8++) v += s_red[w8][tid];
        g_spart[(b * 256 + blin) * 4 + tid] = v;
        __threadfence();
    }
    __syncthreads();
    if (tid == 0) {
        unsigned old = atomicInc(&g_cnt0, NBLK - 1u);
        s_last = (old == NBLK - 1u);
    }
    __syncthreads();
    if (!s_last) return;
    __threadfence();

    // last block: per-batch spec_ctrl MLP -> gamma (warp w = batch w)
    int w8 = tid >> 5, l = tid & 31;
    float S1 = 0, Q1 = 0, S2 = 0, Q2 = 0;
    for (int i = l; i < 256; i += 32) {
        S1 += g_spart[(w8 * 256 + i) * 4 + 0];
        Q1 += g_spart[(w8 * 256 + i) * 4 + 1];
        S2 += g_spart[(w8 * 256 + i) * 4 + 2];
        Q2 += g_spart[(w8 * 256 + i) * 4 + 3];
    }
#pragma unroll
    for (int o = 16; o > 0; o >>= 1) {
        S1 += __shfl_down_sync(0xffffffffu, S1, o);
        Q1 += __shfl_down_sync(0xffffffffu, Q1, o);
        S2 += __shfl_down_sync(0xffffffffu, S2, o);
        Q2 += __shfl_down_sync(0xffffffffu, Q2, o);
    }
    if (l == 0) {
        const float N = (float)PIX;
        float m1 = S1 / N, m2 = S2 / N;
        float v1 = (Q1 - N * m1 * m1) / (N - 1.0f);
        float v2 = (Q2 - N * m2 * m2) / (N - 1.0f);
        float feat[5] = { m1, sqrtf(fmaxf(v1, 0.f)), m2, sqrtf(fmaxf(v2, 0.f)), 1.0f };
        float outv = fc2_b[0];
        for (int j = 0; j < 32; j++) {
            float t = fc1_b[j];
#pragma unroll
            for (int i = 0; i < 5; i++) t += feat[i] * fc1_w[j * 5 + i];
            outv += gelu_f(t) * fc2_w[j];
        }
        g_gamma[w8] = (0.5f + 1.5f * sigmoid_f(outv)) * CFL_SCALE;
    }
}

// ---------------------------------------------------------------------------
// prep: stab2 (16->1 sigmoid -> alpha)  AND  hfix (conv3x3 of [b,m,k] + bias)
// ---------------------------------------------------------------------------
__global__ void __launch_bounds__(256) prep_kernel(
    const float* __restrict__ inp,
    const float* __restrict__ w2s, const float* __restrict__ b2s,
    const float* __restrict__ w1, const float* __restrict__ b1)
{
    const int b = blockIdx.z;
    const int tx0 = blockIdx.x * 16, ty0 = blockIdx.y * 16;
    __shared__ float s_sh[SHID][18][18];
    __shared__ float s_in[3][18][18];
    __shared__ float s_ws[SHID * 9];
    __shared__ __align__(16) float s_wh[27][32];
    __shared__ float s_bh[32];
    int tid = threadIdx.y * 16 + threadIdx.x;

    if (tid < SHID * 9) s_ws[tid] = w2s[tid];
    for (int i = tid; i < HID * 27; i += 256) {
        int oc = i / 27, r = i % 27;
        s_wh[r][oc] = w1[oc * 36 + 9 + r];   // skip z-channel taps
    }
    if (tid < HID) s_bh[tid] = b1[tid];

    const float* hp = g_sh + (size_t)b * SHID * PIX;
    for (int i = tid; i < SHID * 324; i += 256) {
        int c = i / 324, r = i % 324, yy = r / 18, xx = r % 18;
        int gy = ty0 + yy - 1, gx = tx0 + xx - 1;
        float v = 0.f;
        if ((unsigned)gy < 256u && (unsigned)gx < 256u)
            v = hp[c * PIX + gy * WW + gx];
        s_sh[c][yy][xx] = v;
    }
    const float* bp = inp + (size_t)b * 3 * PIX;
    for (int i = tid; i < 3 * 324; i += 256) {
        int c = i / 324, r = i % 324, yy = r / 18, xx = r % 18;
        int gy = ty0 + yy - 1, gx = tx0 + xx - 1;
        float v = 0.f;
        if ((unsigned)gy < 256u && (unsigned)gx < 256u)
            v = bp[c * PIX + gy * WW + gx];
        s_in[c][yy][xx] = v;
    }
    __syncthreads();

    int ty = threadIdx.y, tx = threadIdx.x;
    int pix = (ty0 + ty) * WW + (tx0 + tx);

    // stab2: alpha
    {
        float acc = b2s[0];
#pragma unroll
        for (int c = 0; c < SHID; c++)
#pragma unroll
            for (int ky = 0; ky < 3; ky++)
#pragma unroll
                for (int kx = 0; kx < 3; kx++)
                    acc += s_ws[c * 9 + ky * 3 + kx] * s_sh[c][ty + ky][tx + kx];
        g_alpha[(size_t)b * PIX + pix] = sigmoid_f(acc);
    }

    // hfix: 27-tap conv of fixed channels into 32 outputs
    {
        float acc[HID];
#pragma unroll
        for (int oc = 0; oc < HID; oc++) acc[oc] = s_bh[oc];
#pragma unroll
        for (int c = 0; c < 3; c++)
#pragma unroll
            for (int ky = 0; ky < 3; ky++)
#pragma unroll
                for (int kx = 0; kx < 3; kx++) {
                    float iv = s_in[c][ty + ky][tx + kx];
                    int r = c * 9 + ky * 3 + kx;
#pragma unroll
                    for (int j = 0; j < 8; j++) {
                        float4 w4 = ((const float4*)&s_wh[r][0])[j];
                        acc[4*j+0] += iv * w4.x; acc[4*j+1] += iv * w4.y;
                        acc[4*j+2] += iv * w4.z; acc[4*j+3] += iv * w4.w;
                    }
                }
        float* op = g_hfix + (size_t)b * HID * PIX + pix;
#pragma unroll
        for (int oc = 0; oc < HID; oc++) op[oc * PIX] = acc[oc];
    }
}

// ---------------------------------------------------------------------------
// convz: h = h_fixed + conv3x3(z, w1[:,0])  (9 taps), write g_h + GN partials;
// LAST BLOCK folds GN stats -> scale/shift.
// ---------------------------------------------------------------------------
__global__ void __launch_bounds__(256, 4) convz_kernel(
    const float* __restrict__ w1, const float* __restrict__ gn_w,
    const float* __restrict__ gn_b, int check)
{
    if (check && g_converged) return;
    const int b = blockIdx.z;
    const int tx0 = blockIdx.x * 16, ty0 = blockIdx.y * 16;
    __shared__ float s_z[18][18];
    __shared__ __align__(16) float s_w[9][32];
    __shared__ float s_red[8][8];
    __shared__ bool s_last;
    int tid = threadIdx.y * 16 + threadIdx.x;

    for (int i = tid; i < HID * 9; i += 256) {
        int oc = i / 9, r = i % 9;
        s_w[r][oc] = w1[oc * 36 + r];       // z-channel taps (c=0)
    }

    const float* zp = g_z + b * PIX;
    for (int i = tid; i < 324; i += 256) {
        int yy = i / 18, xx = i % 18;
        int gy = ty0 + yy - 1, gx = tx0 + xx - 1;
        float v = 0.f;
        if ((unsigned)gy < 256u && (unsigned)gx < 256u)
            v = zp[gy * WW + gx];
        s_z[yy][xx] = v;
    }
    __syncthreads();

    int ty = threadIdx.y, tx = threadIdx.x;
    float zv[9];
#pragma unroll
    for (int ky = 0; ky < 3; ky++)
#pragma unroll
        for (int kx = 0; kx < 3; kx++)
            zv[ky * 3 + kx] = s_z[ty + ky][tx + kx];

    int pix = (ty0 + ty) * WW + (tx0 + tx);
    const float* fp = g_hfix + (size_t)b * HID * PIX + pix;
    float acc[HID];
#pragma unroll
    for (int oc = 0; oc < HID; oc++) acc[oc] = fp[oc * PIX];
#pragma unroll
    for (int r = 0; r < 9; r++) {
        float iv = zv[r];
#pragma unroll
        for (int j = 0; j < 8; j++) {
            float4 w4 = ((const float4*)&s_w[r][0])[j];
            acc[4*j+0] += iv * w4.x; acc[4*j+1] += iv * w4.y;
            acc[4*j+2] += iv * w4.z; acc[4*j+3] += iv * w4.w;
        }
    }

    float* hp = g_h + (size_t)b * HID * PIX + pix;
    float gs[4] = {0, 0, 0, 0}, gq[4] = {0, 0, 0, 0};
#pragma unroll
    for (int oc = 0; oc < HID; oc++) {
        float v = acc[oc];
        hp[oc * PIX] = v;
        gs[oc >> 3] += v;
        gq[oc >> 3] += v * v;
    }
#pragma unroll
    for (int o = 16; o > 0; o >>= 1) {
#pragma unroll
        for (int g = 0; g < 4; g++) {
            gs[g] += __shfl_down_sync(0xffffffffu, gs[g], o);
            gq[g] += __shfl_down_sync(0xffffffffu, gq[g], o);
        }
    }
    int lane = tid & 31, warp = tid >> 5;
    if (lane == 0) {
#pragma unroll
        for (int g = 0; g < 4; g++) { s_red[warp][g] = gs[g]; s_red[warp][4 + g] = gq[g]; }
    }
    __syncthreads();
    int blin = blockIdx.y * 16 + blockIdx.x;
    if (tid < 8) {
        float v = 0.f;
#pragma unroll
        for (int w = 0; w < 8; w++) v += s_red[w][tid];
        int g = tid & 3, which = tid >> 2;
        g_part[((b * 256 + blin) * 4 + g) * 2 + which] = v;
        __threadfence();
    }
    __syncthreads();
    if (tid == 0) {
        unsigned old = atomicInc(&g_cnt1, NBLK - 1u);
        s_last = (old == NBLK - 1u);
    }
    __syncthreads();
    if (!s_last) return;
    __threadfence();

    // last block: fold GN stats for all 32 (b,g) pairs; 8 lanes per pair
    int pair = tid >> 3, l8 = tid & 7;
    int bb = pair >> 2, g = pair & 3;
    float s = 0.f, q = 0.f;
    for (int i = l8; i < 256; i += 8) {
        s += g_part[((bb * 256 + i) * 4 + g) * 2 + 0];
        q += g_part[((bb * 256 + i) * 4 + g) * 2 + 1];
    }
#pragma unroll
    for (int o = 4; o > 0; o >>= 1) {
        s += __shfl_down_sync(0xffffffffu, s, o, 8);
        q += __shfl_down_sync(0xffffffffu, q, o, 8);
    }
    if (l8 == 0) {
        const float invN = 1.0f / (float)(CPG * PIX);
        float mean = s * invN;
        float Qn = q * invN;
        float var = isinf(Qn) ? Qn : fmaxf(Qn - mean * mean, 0.0f);
        float rstd = rsqrtf(var + EPS);       // var=inf -> rstd=0
#pragma unroll
        for (int c = 0; c < CPG; c++) {
            int gc = g * CPG + c;
            float sc = gn_w[gc] * rstd;
            g_scale[bb * HID + gc] = sc;
            g_shift[bb * HID + gc] = (rstd == 0.0f) ? gn_b[gc] : (gn_b[gc] - mean * sc);
        }
    }
}

// ---------------------------------------------------------------------------
// fused2: GN->GELU->conv2(32->1)->damped update; LAST BLOCK folds diff.
// Tile 32x8 (block (32,8)): warp = one 32-wide row -> conflict-free conv LDS.
// Normal path FILL8 staging; FAST path (all sc==0) = constant-dz shortcut.
// ---------------------------------------------------------------------------
// fill one pixel (yy,xx) of the [10][34] halo for channels [base, base+8)
#define FILL8(base, yy, xx, inb, hb)                                       \
    {                                                                      \
        float hv[8];                                                       \
        _Pragma("unroll")                                                  \
        for (int c = 0; c < 8; c++)                                        \
            hv[c] = (inb) ? (hb)[(base + c) * PIX] : 0.f;                  \
        _Pragma("unroll")                                                  \
        for (int c = 0; c < 8; c++) {                                      \
            float sc = s_sc[base + c];                                     \
            float t = (sc == 0.0f) ? s_sf[base + c]                        \
                                   : (hv[c] * sc + s_sf[base + c]);        \
            s_h[base + c][yy][xx] = (inb) ? gelu_f(t) : 0.f;               \
        }                                                                  \
    }

__global__ void __launch_bounds__(256, 3) fused2_kernel(
    const float* __restrict__ inp, const float* __restrict__ w2,
    const float* __restrict__ b2, float* __restrict__ final_out, int mode)
{
    if (mode == 0 && g_converged) return;
    const int b = blockIdx.z;
    const int tx0 = blockIdx.x * 32, ty0 = blockIdx.y * 8;
    __shared__ float s_h[HID][10][34];
    __shared__ float s_w[HID * 9];
    __shared__ float s_sc[HID], s_sf[HID];
    __shared__ float s_G[HID];
    __shared__ float s_red[8];
    __shared__ float s_Dfull;
    __shared__ bool s_fast;
    __shared__ bool s_last;
    int tid = threadIdx.y * 32 + threadIdx.x;

    for (int i = tid; i < HID * 9; i += 256) s_w[i] = w2[i];
    if (tid < HID) { s_sc[tid] = g_scale[b * HID + tid]; s_sf[tid] = g_shift[b * HID + tid]; }
    __syncthreads();

    // warp 0: overflow fast-path detection + constant-G precompute
    if (tid < 32) {
        int zero = (s_sc[tid] == 0.0f);
        unsigned bal = __ballot_sync(0xffffffffu, zero);
        float wsum = 0.f;
#pragma unroll
        for (int j = 0; j < 9; j++) wsum += s_w[tid * 9 + j];
        float Gc = gelu_f(s_sf[tid]);     // == gelu(gn_b) when sc==0
        s_G[tid] = Gc;
        float t = Gc * wsum;
#pragma unroll
        for (int o = 16; o > 0; o >>= 1) t += __shfl_down_sync(0xffffffffu, t, o);
        if (tid == 0) { s_fast = (bal == 0xffffffffu); s_Dfull = t; }
    }
    __syncthreads();

    int ty = threadIdx.y, tx = threadIdx.x;
    float acc;

    if (s_fast) {
        // all sc==0: G constant per channel; dz depends only on valid-tap mask
        int Y = ty0 + ty, X = tx0 + tx;
        bool interior = (Y >= 1) && (Y <= 254) && (X >= 1) && (X <= 254);
        if (interior) {
            acc = b2[0] + s_Dfull;
        } else {
            acc = b2[0];
            int ky0 = (Y == 0) ? 1 : 0, ky1 = (Y == 255) ? 2 : 3;
            int kx0 = (X == 0) ? 1 : 0, kx1 = (X == 255) ? 2 : 3;
            for (int c = 0; c < HID; c++) {
                float wsum = 0.f;
                for (int ky = ky0; ky < ky1; ky++)
                    for (int kx = kx0; kx < kx1; kx++)
                        wsum += s_w[c * 9 + ky * 3 + kx];
                acc += s_G[c] * wsum;
            }
        }
    } else {
        const float* hp = g_h + (size_t)b * HID * PIX;
        {
            // halo = 10 rows x 34 cols = 340 pixels
            // pixel 1: p = tid (tid < 340 always)
            int yy = tid / 34, xx = tid % 34;
            int gy = ty0 + yy - 1, gx = tx0 + xx - 1;
            bool inb = ((unsigned)gy < 256u) && ((unsigned)gx < 256u);
            const float* hb = hp + (inb ? (gy * WW + gx) : 0);
            FILL8(0, yy, xx, inb, hb)
            FILL8(8, yy, xx, inb, hb)
            FILL8(16, yy, xx, inb, hb)
            FILL8(24, yy, xx, inb, hb)
            // pixel 2: p = tid + 256 (only tid < 84)
            if (tid < 84) {
                int p2 = tid + 256;
                int yy2 = p2 / 34, xx2 = p2 % 34;
                int gy2 = ty0 + yy2 - 1, gx2 = tx0 + xx2 - 1;
                bool inb2 = ((unsigned)gy2 < 256u) && ((unsigned)gx2 < 256u);
                const float* hb2 = hp + (inb2 ? (gy2 * WW + gx2) : 0);
                FILL8(0, yy2, xx2, inb2, hb2)
                FILL8(8, yy2, xx2, inb2, hb2)
                FILL8(16, yy2, xx2, inb2, hb2)
                FILL8(24, yy2, xx2, inb2, hb2)
            }
        }
        __syncthreads();

        float a0 = 0.f, a1 = 0.f, a2 = 0.f, a3 = 0.f;   // 4 ILP chains over c%4
#pragma unroll
        for (int c = 0; c < HID; c += 4) {
#pragma unroll
            for (int ky = 0; ky < 3; ky++)
#pragma unroll
                for (int kx = 0; kx < 3; kx++) {
                    int pos = ky * 3 + kx;
                    a0 += s_w[(c + 0) * 9 + pos] * s_h[c + 0][ty + ky][tx + kx];
                    a1 += s_w[(c + 1) * 9 + pos] * s_h[c + 1][ty + ky][tx + kx];
                    a2 += s_w[(c + 2) * 9 + pos] * s_h[c + 2][ty + ky][tx + kx];
                    a3 += s_w[(c + 3) * 9 + pos] * s_h[c + 3][ty + ky][tx + kx];
                }
        }
        acc = b2[0] + ((a0 + a1) + (a2 + a3));
    }

    int pix = (ty0 + ty) * WW + (tx0 + tx);
    int off = b * PIX + pix;
    const float* bp = inp + (size_t)b * 3 * PIX;
    float zold = g_z[off];
    // mirror XLA elementwise rounding exactly (no FMA contraction)
    float ga   = __fmul_rn(g_gamma[b], g_alpha[off]);
    float znew = __fadd_rn(zold, __fmul_rn(ga, acc));
    float m  = bp[PIX + pix];
    float bv = bp[pix];
    float res = __fadd_rn(__fmul_rn(znew, __fadd_rn(1.0f, -m)), __fmul_rn(bv, m));

    if (mode != 0) { final_out[off] = res; return; }

    g_z[off] = res;
    float d = __fadd_rn(res, -zold);
    float s = d * d;
#pragma unroll
    for (int o = 16; o > 0; o >>= 1) s += __shfl_down_sync(0xffffffffu, s, o);
    int lane = tid & 31, warp = tid >> 5;
    if (lane == 0) s_red[warp] = s;
    __syncthreads();
    int blin = blockIdx.y * 8 + blockIdx.x;   // grid (8, 32): 256 blocks/batch
    if (tid == 0) {
        float t = 0.f;
#pragma unroll
        for (int w = 0; w < 8; w++) t += s_red[w];
        g_diffpart[b * 256 + blin] = t;
        __threadfence();
        unsigned old = atomicInc(&g_cnt2, NBLK - 1u);
        s_last = (old == NBLK - 1u);
    }
    __syncthreads();
    if (!s_last) return;
    __threadfence();

    // last block: diff = mean_b ||dz_b||; jax cond continues while diff>=TOL
    int w = tid >> 5, l = tid & 31;
    float t = 0.f;
    for (int i = l; i < 256; i += 32) t += g_diffpart[w * 256 + i];
#pragma unroll
    for (int o = 16; o > 0; o >>= 1) t += __shfl_down_sync(0xffffffffu, t, o);
    __shared__ float sb[8];
    if (l == 0) sb[w] = sqrtf(t);
    __syncthreads();
    if (tid == 0) {
        float mm = 0.f;
#pragma unroll
        for (int bb = 0; bb < 8; bb++) mm += sb[bb];
        mm *= 0.125f;
        if (!(mm >= TOL)) g_converged = 1;   // NaN also stops (matches jax)
    }
}

// ---------------------------------------------------------------------------
extern "C" void kernel_launch(void* const* d_in, const int* in_sizes, int n_in,
                              void* d_out, int out_size)
{
    const float* inp     = (const float*)d_in[0];
    const float* core_w1 = (const float*)d_in[1];
    const float* core_b1 = (const float*)d_in[2];
    const float* gn_w    = (const float*)d_in[3];
    const float* gn_b    = (const float*)d_in[4];
    const float* core_w2 = (const float*)d_in[5];
    const float* core_b2 = (const float*)d_in[6];
    const float* stab_w1 = (const float*)d_in[7];
    const float* stab_b1 = (const float*)d_in[8];
    const float* stab_w2 = (const float*)d_in[9];
    const float* stab_b2 = (const float*)d_in[10];
    const float* fc1_w   = (const float*)d_in[11];
    const float* fc1_b   = (const float*)d_in[12];
    const float* fc2_w   = (const float*)d_in[13];
    const float* fc2_b   = (const float*)d_in[14];
    float* out = (float*)d_out;

    dim3 blk(16, 16);
    dim3 grd(16, 16, BATCH);
    dim3 blkF(32, 8);
    dim3 grdF(8, 32, BATCH);      // 32-wide x 8-high tiles

    // fused2 is the 4th launch (ncu capture window; iter-1 normal path)
    stab1_kernel<<<grd, blk>>>(inp, stab_w1, stab_b1, fc1_w, fc1_b, fc2_w, fc2_b);
    prep_kernel<<<grd, blk>>>(inp, stab_w2, stab_b2, core_w1, core_b1);
    convz_kernel<<<grd, blk>>>(core_w1, gn_w, gn_b, 1);
    fused2_kernel<<<grdF, blkF>>>(inp, core_w2, core_b2, nullptr, 0);

    for (int it = 1; it < MAX_ITER; ++it) {
        convz_kernel<<<grd, blk>>>(core_w1, gn_w, gn_b, 1);
        fused2_kernel<<<grdF, blkF>>>(inp, core_w2, core_b2, nullptr, 0);
    }
    // final core_f (always runs): z_star -> d_out
    convz_kernel<<<grd, blk>>>(core_w1, gn_w, gn_b, 0);
    fused2_kernel<<<grdF, blkF>>>(inp, core_w2, core_b2, out, 1);
}

// round 13
// speedup vs baseline: 1.3858x; 1.0041x over previous
#include <cuda_runtime.h>
#include <cuda_bf16.h>
#include <math.h>

// ---------------------------------------------------------------------------
// MultiDEQPDEBlock: DEQ fixed-point PDE solver  (B=8, 256x256, hid=32, GN4)
// core_f: conv3x3(4->32) -> GN(4) -> GELU(erf) -> conv3x3(32->1) -> damped update
// h_fixed (conv of loop-invariant [b,m,k]) precomputed once; per-iter conv1 is
// the 9-tap z convolution. fused2: 32x8 tile (conflict-free), conv loop uses
// CHANNEL-PAIRED smem + fma.rn.f32x2 -> issue slots halved (864 -> 432).
// FAST PATH (all GN groups of a batch overflowed): G=gelu(gn_b) constant ->
// dz = tap-mask-weighted constant. Divergent dynamics (|1-mask|>1) -> ~1e37;
// overflow paths mirror jax (var->inf, rstd->0, xn->0; NaN diff stops loop).
// ---------------------------------------------------------------------------

#define BATCH 8
#define HH 256
#define WW 256
#define PIX (HH*WW)
#define HID 32
#define SHID 16
#define GROUPS 4
#define CPG 8
#define EPS 1e-5f
#define TOL 1e-4f
#define MAX_ITER 50
#define CFL_SCALE 0.015625f
#define NBLK 2048               // 2048 blocks in iter-kernels' grids

// ---- scratch (device globals; no cudaMalloc allowed) ----
__device__ float g_h[(size_t)BATCH*HID*PIX];      // 64 MB conv1 output (pre-GN)
__device__ float g_hfix[(size_t)BATCH*HID*PIX];   // 64 MB conv of fixed channels
__device__ float g_sh[(size_t)BATCH*SHID*PIX];    // 32 MB stabilizer hidden
__device__ float g_alpha[(size_t)BATCH*PIX];
__device__ float g_z[(size_t)BATCH*PIX];
__device__ float g_gamma[BATCH];
__device__ float g_part[BATCH*256*GROUPS*2];
__device__ float g_spart[BATCH*256*4];
__device__ float g_scale[BATCH*HID];
__device__ float g_shift[BATCH*HID];
__device__ float g_diffpart[BATCH*256];
__device__ int   g_converged;
__device__ unsigned g_cnt0;     // zero-init; self-resetting via atomicInc wrap
__device__ unsigned g_cnt1;
__device__ unsigned g_cnt2;

__device__ __forceinline__ float gelu_f(float x) {
    return 0.5f * x * (1.0f + erff(x * 0.70710678118654752f));
}
__device__ __forceinline__ float sigmoid_f(float x) {
    return 1.0f / (1.0f + expf(-x));
}

// packed fp32x2 FMA (exact pairwise fp32 semantics)
#define FMA2(acc, a, bb) asm("fma.rn.f32x2 %0, %1, %2, %0;" : "+l"(acc) : "l"(a), "l"(bb))
#define UNPACK2(lo, hi, v) asm("mov.b64 {%0, %1}, %2;" : "=f"(lo), "=f"(hi) : "l"(v))

// ---------------------------------------------------------------------------
// stabilizer conv1 (3->16, GELU) + z init + spec partials; last block: gamma MLP
// ---------------------------------------------------------------------------
__global__ void __launch_bounds__(256) stab1_kernel(
    const float* __restrict__ inp, const float* __restrict__ w,
    const float* __restrict__ bias,
    const float* __restrict__ fc1_w, const float* __restrict__ fc1_b,
    const float* __restrict__ fc2_w, const float* __restrict__ fc2_b)
{
    const int b = blockIdx.z;
    const int tx0 = blockIdx.x * 16, ty0 = blockIdx.y * 16;
    __shared__ float s_in[3][18][18];
    __shared__ float s_w[27][16];
    __shared__ float s_b[16];
    __shared__ float s_red[8][4];
    __shared__ bool s_last;
    int tid = threadIdx.y * 16 + threadIdx.x;

    if (tid == 0 && blockIdx.x == 0 && blockIdx.y == 0 && b == 0) g_converged = 0;

    for (int i = tid; i < SHID * 27; i += 256) {
        int oc = i / 27, r = i % 27;
        s_w[r][oc] = w[i];
    }
    if (tid < SHID) s_b[tid] = bias[tid];

    const float* bp = inp + (size_t)b * 3 * PIX;
    for (int i = tid; i < 3 * 324; i += 256) {
        int c = i / 324, r = i % 324, yy = r / 18, xx = r % 18;
        int gy = ty0 + yy - 1, gx = tx0 + xx - 1;
        float v = 0.f;
        if ((unsigned)gy < 256u && (unsigned)gx < 256u)
            v = bp[c * PIX + gy * WW + gx];
        s_in[c][yy][xx] = v;
    }
    __syncthreads();

    int ty = threadIdx.y, tx = threadIdx.x;
    float in[27];
#pragma unroll
    for (int c = 0; c < 3; c++)
#pragma unroll
        for (int ky = 0; ky < 3; ky++)
#pragma unroll
            for (int kx = 0; kx < 3; kx++)
                in[c * 9 + ky * 3 + kx] = s_in[c][ty + ky][tx + kx];

    float acc[SHID];
#pragma unroll
    for (int oc = 0; oc < SHID; oc++) acc[oc] = s_b[oc];
#pragma unroll
    for (int r = 0; r < 27; r++) {
        float iv = in[r];
#pragma unroll
        for (int oc = 0; oc < SHID; oc++) acc[oc] += iv * s_w[r][oc];
    }

    int pix = (ty0 + ty) * WW + (tx0 + tx);
    float* out = g_sh + (size_t)b * SHID * PIX + pix;
#pragma unroll
    for (int oc = 0; oc < SHID; oc++)
        out[oc * PIX] = gelu_f(acc[oc]);

    // z init (channel 0 = boundary)
    g_z[b * PIX + pix] = s_in[0][ty + 1][tx + 1];

    // spec partials: |boundary| and k stats
    float bv = fabsf(s_in[0][ty + 1][tx + 1]);
    float kv = s_in[2][ty + 1][tx + 1];
    float s1 = bv, q1 = bv * bv, s2 = kv, q2 = kv * kv;
#pragma unroll
    for (int o = 16; o > 0; o >>= 1) {
        s1 += __shfl_down_sync(0xffffffffu, s1, o);
        q1 += __shfl_down_sync(0xffffffffu, q1, o);
        s2 += __shfl_down_sync(0xffffffffu, s2, o);
        q2 += __shfl_down_sync(0xffffffffu, q2, o);
    }
    int lane = tid & 31, warp = tid >> 5;
    if (lane == 0) { s_red[warp][0] = s1; s_red[warp][1] = q1; s_red[warp][2] = s2; s_red[warp][3] = q2; }
    __syncthreads();
    int blin = blockIdx.y * 16 + blockIdx.x;
    if (tid < 4) {
        float v = 0.f;
#pragma unroll
        for (int w8 = 0; w8 < 8; w8++) v += s_red[w8][tid];
        g_spart[(b * 256 + blin) * 4 + tid] = v;
        __threadfence();
    }
    __syncthreads();
    if (tid == 0) {
        unsigned old = atomicInc(&g_cnt0, NBLK - 1u);
        s_last = (old == NBLK - 1u);
    }
    __syncthreads();
    if (!s_last) return;
    __threadfence();

    // last block: per-batch spec_ctrl MLP -> gamma (warp w = batch w)
    int w8 = tid >> 5, l = tid & 31;
    float S1 = 0, Q1 = 0, S2 = 0, Q2 = 0;
    for (int i = l; i < 256; i += 32) {
        S1 += g_spart[(w8 * 256 + i) * 4 + 0];
        Q1 += g_spart[(w8 * 256 + i) * 4 + 1];
        S2 += g_spart[(w8 * 256 + i) * 4 + 2];
        Q2 += g_spart[(w8 * 256 + i) * 4 + 3];
    }
#pragma unroll
    for (int o = 16; o > 0; o >>= 1) {
        S1 += __shfl_down_sync(0xffffffffu, S1, o);
        Q1 += __shfl_down_sync(0xffffffffu, Q1, o);
        S2 += __shfl_down_sync(0xffffffffu, S2, o);
        Q2 += __shfl_down_sync(0xffffffffu, Q2, o);
    }
    if (l == 0) {
        const float N = (float)PIX;
        float m1 = S1 / N, m2 = S2 / N;
        float v1 = (Q1 - N * m1 * m1) / (N - 1.0f);
        float v2 = (Q2 - N * m2 * m2) / (N - 1.0f);
        float feat[5] = { m1, sqrtf(fmaxf(v1, 0.f)), m2, sqrtf(fmaxf(v2, 0.f)), 1.0f };
        float outv = fc2_b[0];
        for (int j = 0; j < 32; j++) {
            float t = fc1_b[j];
#pragma unroll
            for (int i = 0; i < 5; i++) t += feat[i] * fc1_w[j * 5 + i];
            outv += gelu_f(t) * fc2_w[j];
        }
        g_gamma[w8] = (0.5f + 1.5f * sigmoid_f(outv)) * CFL_SCALE;
    }
}

// ---------------------------------------------------------------------------
// prep: stab2 (16->1 sigmoid -> alpha)  AND  hfix (conv3x3 of [b,m,k] + bias)
// ---------------------------------------------------------------------------
__global__ void __launch_bounds__(256) prep_kernel(
    const float* __restrict__ inp,
    const float* __restrict__ w2s, const float* __restrict__ b2s,
    const float* __restrict__ w1, const float* __restrict__ b1)
{
    const int b = blockIdx.z;
    const int tx0 = blockIdx.x * 16, ty0 = blockIdx.y * 16;
    __shared__ float s_sh[SHID][18][18];
    __shared__ float s_in[3][18][18];
    __shared__ float s_ws[SHID * 9];
    __shared__ __align__(16) float s_wh[27][32];
    __shared__ float s_bh[32];
    int tid = threadIdx.y * 16 + threadIdx.x;

    if (tid < SHID * 9) s_ws[tid] = w2s[tid];
    for (int i = tid; i < HID * 27; i += 256) {
        int oc = i / 27, r = i % 27;
        s_wh[r][oc] = w1[oc * 36 + 9 + r];   // skip z-channel taps
    }
    if (tid < HID) s_bh[tid] = b1[tid];

    const float* hp = g_sh + (size_t)b * SHID * PIX;
    for (int i = tid; i < SHID * 324; i += 256) {
        int c = i / 324, r = i % 324, yy = r / 18, xx = r % 18;
        int gy = ty0 + yy - 1, gx = tx0 + xx - 1;
        float v = 0.f;
        if ((unsigned)gy < 256u && (unsigned)gx < 256u)
            v = hp[c * PIX + gy * WW + gx];
        s_sh[c][yy][xx] = v;
    }
    const float* bp = inp + (size_t)b * 3 * PIX;
    for (int i = tid; i < 3 * 324; i += 256) {
        int c = i / 324, r = i % 324, yy = r / 18, xx = r % 18;
        int gy = ty0 + yy - 1, gx = tx0 + xx - 1;
        float v = 0.f;
        if ((unsigned)gy < 256u && (unsigned)gx < 256u)
            v = bp[c * PIX + gy * WW + gx];
        s_in[c][yy][xx] = v;
    }
    __syncthreads();

    int ty = threadIdx.y, tx = threadIdx.x;
    int pix = (ty0 + ty) * WW + (tx0 + tx);

    // stab2: alpha
    {
        float acc = b2s[0];
#pragma unroll
        for (int c = 0; c < SHID; c++)
#pragma unroll
            for (int ky = 0; ky < 3; ky++)
#pragma unroll
                for (int kx = 0; kx < 3; kx++)
                    acc += s_ws[c * 9 + ky * 3 + kx] * s_sh[c][ty + ky][tx + kx];
        g_alpha[(size_t)b * PIX + pix] = sigmoid_f(acc);
    }

    // hfix: 27-tap conv of fixed channels into 32 outputs
    {
        float acc[HID];
#pragma unroll
        for (int oc = 0; oc < HID; oc++) acc[oc] = s_bh[oc];
#pragma unroll
        for (int c = 0; c < 3; c++)
#pragma unroll
            for (int ky = 0; ky < 3; ky++)
#pragma unroll
                for (int kx = 0; kx < 3; kx++) {
                    float iv = s_in[c][ty + ky][tx + kx];
                    int r = c * 9 + ky * 3 + kx;
#pragma unroll
                    for (int j = 0; j < 8; j++) {
                        float4 w4 = ((const float4*)&s_wh[r][0])[j];
                        acc[4*j+0] += iv * w4.x; acc[4*j+1] += iv * w4.y;
                        acc[4*j+2] += iv * w4.z; acc[4*j+3] += iv * w4.w;
                    }
                }
        float* op = g_hfix + (size_t)b * HID * PIX + pix;
#pragma unroll
        for (int oc = 0; oc < HID; oc++) op[oc * PIX] = acc[oc];
    }
}

// ---------------------------------------------------------------------------
// convz: h = h_fixed + conv3x3(z, w1[:,0])  (9 taps), write g_h + GN partials;
// LAST BLOCK folds GN stats -> scale/shift.
// ---------------------------------------------------------------------------
__global__ void __launch_bounds__(256, 4) convz_kernel(
    const float* __restrict__ w1, const float* __restrict__ gn_w,
    const float* __restrict__ gn_b, int check)
{
    if (check && g_converged) return;
    const int b = blockIdx.z;
    const int tx0 = blockIdx.x * 16, ty0 = blockIdx.y * 16;
    __shared__ float s_z[18][18];
    __shared__ __align__(16) float s_w[9][32];
    __shared__ float s_red[8][8];
    __shared__ bool s_last;
    int tid = threadIdx.y * 16 + threadIdx.x;

    for (int i = tid; i < HID * 9; i += 256) {
        int oc = i / 9, r = i % 9;
        s_w[r][oc] = w1[oc * 36 + r];       // z-channel taps (c=0)
    }

    const float* zp = g_z + b * PIX;
    for (int i = tid; i < 324; i += 256) {
        int yy = i / 18, xx = i % 18;
        int gy = ty0 + yy - 1, gx = tx0 + xx - 1;
        float v = 0.f;
        if ((unsigned)gy < 256u && (unsigned)gx < 256u)
            v = zp[gy * WW + gx];
        s_z[yy][xx] = v;
    }
    __syncthreads();

    int ty = threadIdx.y, tx = threadIdx.x;
    float zv[9];
#pragma unroll
    for (int ky = 0; ky < 3; ky++)
#pragma unroll
        for (int kx = 0; kx < 3; kx++)
            zv[ky * 3 + kx] = s_z[ty + ky][tx + kx];

    int pix = (ty0 + ty) * WW + (tx0 + tx);
    const float* fp = g_hfix + (size_t)b * HID * PIX + pix;
    float acc[HID];
#pragma unroll
    for (int oc = 0; oc < HID; oc++) acc[oc] = fp[oc * PIX];
#pragma unroll
    for (int r = 0; r < 9; r++) {
        float iv = zv[r];
#pragma unroll
        for (int j = 0; j < 8; j++) {
            float4 w4 = ((const float4*)&s_w[r][0])[j];
            acc[4*j+0] += iv * w4.x; acc[4*j+1] += iv * w4.y;
            acc[4*j+2] += iv * w4.z; acc[4*j+3] += iv * w4.w;
        }
    }

    float* hp = g_h + (size_t)b * HID * PIX + pix;
    float gs[4] = {0, 0, 0, 0}, gq[4] = {0, 0, 0, 0};
#pragma unroll
    for (int oc = 0; oc < HID; oc++) {
        float v = acc[oc];
        hp[oc * PIX] = v;
        gs[oc >> 3] += v;
        gq[oc >> 3] += v * v;
    }
#pragma unroll
    for (int o = 16; o > 0; o >>= 1) {
#pragma unroll
        for (int g = 0; g < 4; g++) {
            gs[g] += __shfl_down_sync(0xffffffffu, gs[g], o);
            gq[g] += __shfl_down_sync(0xffffffffu, gq[g], o);
        }
    }
    int lane = tid & 31, warp = tid >> 5;
    if (lane == 0) {
#pragma unroll
        for (int g = 0; g < 4; g++) { s_red[warp][g] = gs[g]; s_red[warp][4 + g] = gq[g]; }
    }
    __syncthreads();
    int blin = blockIdx.y * 16 + blockIdx.x;
    if (tid < 8) {
        float v = 0.f;
#pragma unroll
        for (int w = 0; w < 8; w++) v += s_red[w][tid];
        int g = tid & 3, which = tid >> 2;
        g_part[((b * 256 + blin) * 4 + g) * 2 + which] = v;
        __threadfence();
    }
    __syncthreads();
    if (tid == 0) {
        unsigned old = atomicInc(&g_cnt1, NBLK - 1u);
        s_last = (old == NBLK - 1u);
    }
    __syncthreads();
    if (!s_last) return;
    __threadfence();

    // last block: fold GN stats for all 32 (b,g) pairs; 8 lanes per pair
    int pair = tid >> 3, l8 = tid & 7;
    int bb = pair >> 2, g = pair & 3;
    float s = 0.f, q = 0.f;
    for (int i = l8; i < 256; i += 8) {
        s += g_part[((bb * 256 + i) * 4 + g) * 2 + 0];
        q += g_part[((bb * 256 + i) * 4 + g) * 2 + 1];
    }
#pragma unroll
    for (int o = 4; o > 0; o >>= 1) {
        s += __shfl_down_sync(0xffffffffu, s, o, 8);
        q += __shfl_down_sync(0xffffffffu, q, o, 8);
    }
    if (l8 == 0) {
        const float invN = 1.0f / (float)(CPG * PIX);
        float mean = s * invN;
        float Qn = q * invN;
        float var = isinf(Qn) ? Qn : fmaxf(Qn - mean * mean, 0.0f);
        float rstd = rsqrtf(var + EPS);       // var=inf -> rstd=0
#pragma unroll
        for (int c = 0; c < CPG; c++) {
            int gc = g * CPG + c;
            float sc = gn_w[gc] * rstd;
            g_scale[bb * HID + gc] = sc;
            g_shift[bb * HID + gc] = (rstd == 0.0f) ? gn_b[gc] : (gn_b[gc] - mean * sc);
        }
    }
}

// ---------------------------------------------------------------------------
// fused2: GN->GELU->conv2(32->1)->damped update; LAST BLOCK folds diff.
// Tile 32x8, channel-PAIRED s_h + fma.rn.f32x2 conv loop (432 issue slots).
// Normal path FILL8 staging; FAST path (all sc==0) = constant-dz shortcut.
// ---------------------------------------------------------------------------
// fill one halo pixel (yy,xx) for channels [base, base+8) into paired layout
#define FILL8(base, yy, xx, inb, hb)                                       \
    {                                                                      \
        float hv[8];                                                       \
        _Pragma("unroll")                                                  \
        for (int c = 0; c < 8; c++)                                        \
            hv[c] = (inb) ? (hb)[(base + c) * PIX] : 0.f;                  \
        _Pragma("unroll")                                                  \
        for (int c = 0; c < 8; c++) {                                      \
            float sc = s_sc[base + c];                                     \
            float t = (sc == 0.0f) ? s_sf[base + c]                        \
                                   : (hv[c] * sc + s_sf[base + c]);        \
            s_h[(base + c) >> 1][yy][xx][(base + c) & 1] =                 \
                (inb) ? gelu_f(t) : 0.f;                                   \
        }                                                                  \
    }

__global__ void __launch_bounds__(256, 3) fused2_kernel(
    const float* __restrict__ inp, const float* __restrict__ w2,
    const float* __restrict__ b2, float* __restrict__ final_out, int mode)
{
    if (mode == 0 && g_converged) return;
    const int b = blockIdx.z;
    const int tx0 = blockIdx.x * 32, ty0 = blockIdx.y * 8;
    __shared__ __align__(8) float s_h[16][10][34][2];   // channel-paired
    __shared__ __align__(8) float s_wp[9][16][2];       // [pos][c2][elem]
    __shared__ float s_sc[HID], s_sf[HID];
    __shared__ float s_G[HID];
    __shared__ float s_red[8];
    __shared__ float s_Dfull;
    __shared__ bool s_fast;
    __shared__ bool s_last;
    int tid = threadIdx.y * 32 + threadIdx.x;

    for (int i = tid; i < HID * 9; i += 256) {
        int c = i / 9, pos = i % 9;
        s_wp[pos][c >> 1][c & 1] = w2[i];
    }
    if (tid < HID) { s_sc[tid] = g_scale[b * HID + tid]; s_sf[tid] = g_shift[b * HID + tid]; }
    __syncthreads();

    // warp 0: overflow fast-path detection + constant-G precompute
    if (tid < 32) {
        int zero = (s_sc[tid] == 0.0f);
        unsigned bal = __ballot_sync(0xffffffffu, zero);
        float wsum = 0.f;
#pragma unroll
        for (int j = 0; j < 9; j++) wsum += s_wp[j][tid >> 1][tid & 1];
        float Gc = gelu_f(s_sf[tid]);     // == gelu(gn_b) when sc==0
        s_G[tid] = Gc;
        float t = Gc * wsum;
#pragma unroll
        for (int o = 16; o > 0; o >>= 1) t += __shfl_down_sync(0xffffffffu, t, o);
        if (tid == 0) { s_fast = (bal == 0xffffffffu); s_Dfull = t; }
    }
    __syncthreads();

    int ty = threadIdx.y, tx = threadIdx.x;
    float acc;

    if (s_fast) {
        // all sc==0: G constant per channel; dz depends only on valid-tap mask
        int Y = ty0 + ty, X = tx0 + tx;
        bool interior = (Y >= 1) && (Y <= 254) && (X >= 1) && (X <= 254);
        if (interior) {
            acc = b2[0] + s_Dfull;
        } else {
            acc = b2[0];
            int ky0 = (Y == 0) ? 1 : 0, ky1 = (Y == 255) ? 2 : 3;
            int kx0 = (X == 0) ? 1 : 0, kx1 = (X == 255) ? 2 : 3;
            for (int c = 0; c < HID; c++) {
                float wsum = 0.f;
                for (int ky = ky0; ky < ky1; ky++)
                    for (int kx = kx0; kx < kx1; kx++)
                        wsum += s_wp[ky * 3 + kx][c >> 1][c & 1];
                acc += s_G[c] * wsum;
            }
        }
    } else {
        const float* hp = g_h + (size_t)b * HID * PIX;
        {
            // halo = 10 rows x 34 cols = 340 pixels
            // pixel 1: p = tid (tid < 340 always)
            int yy = tid / 34, xx = tid % 34;
            int gy = ty0 + yy - 1, gx = tx0 + xx - 1;
            bool inb = ((unsigned)gy < 256u) && ((unsigned)gx < 256u);
            const float* hb = hp + (inb ? (gy * WW + gx) : 0);
            FILL8(0, yy, xx, inb, hb)
            FILL8(8, yy, xx, inb, hb)
            FILL8(16, yy, xx, inb, hb)
            FILL8(24, yy, xx, inb, hb)
            // pixel 2: p = tid + 256 (only tid < 84)
            if (tid < 84) {
                int p2 = tid + 256;
                int yy2 = p2 / 34, xx2 = p2 % 34;
                int gy2 = ty0 + yy2 - 1, gx2 = tx0 + xx2 - 1;
                bool inb2 = ((unsigned)gy2 < 256u) && ((unsigned)gx2 < 256u);
                const float* hb2 = hp + (inb2 ? (gy2 * WW + gx2) : 0);
                FILL8(0, yy2, xx2, inb2, hb2)
                FILL8(8, yy2, xx2, inb2, hb2)
                FILL8(16, yy2, xx2, inb2, hb2)
                FILL8(24, yy2, xx2, inb2, hb2)
            }
        }
        __syncthreads();

        // channel-paired conv: 144 LDS.64 + 144 bcast LDS.64 + 144 FFMA2
        unsigned long long pa[4] = {0ull, 0ull, 0ull, 0ull};
#pragma unroll
        for (int c2 = 0; c2 < 16; c2++) {
#pragma unroll
            for (int ky = 0; ky < 3; ky++)
#pragma unroll
                for (int kx = 0; kx < 3; kx++) {
                    int pos = ky * 3 + kx;
                    unsigned long long h2 =
                        *(const unsigned long long*)&s_h[c2][ty + ky][tx + kx][0];
                    unsigned long long w2p =
                        *(const unsigned long long*)&s_wp[pos][c2][0];
                    FMA2(pa[(c2 * 9 + pos) & 3], h2, w2p);
                }
        }
        float lo0, hi0, lo1, hi1, lo2, hi2, lo3, hi3;
        UNPACK2(lo0, hi0, pa[0]);
        UNPACK2(lo1, hi1, pa[1]);
        UNPACK2(lo2, hi2, pa[2]);
        UNPACK2(lo3, hi3, pa[3]);
        acc = b2[0] + (((lo0 + hi0) + (lo1 + hi1)) + ((lo2 + hi2) + (lo3 + hi3)));
    }

    int pix = (ty0 + ty) * WW + (tx0 + tx);
    int off = b * PIX + pix;
    const float* bp = inp + (size_t)b * 3 * PIX;
    float zold = g_z[off];
    // mirror XLA elementwise rounding exactly (no FMA contraction)
    float ga   = __fmul_rn(g_gamma[b], g_alpha[off]);
    float znew = __fadd_rn(zold, __fmul_rn(ga, acc));
    float m  = bp[PIX + pix];
    float bv = bp[pix];
    float res = __fadd_rn(__fmul_rn(znew, __fadd_rn(1.0f, -m)), __fmul_rn(bv, m));

    if (mode != 0) { final_out[off] = res; return; }

    g_z[off] = res;
    float d = __fadd_rn(res, -zold);
    float s = d * d;
#pragma unroll
    for (int o = 16; o > 0; o >>= 1) s += __shfl_down_sync(0xffffffffu, s, o);
    int lane = tid & 31, warp = tid >> 5;
    if (lane == 0) s_red[warp] = s;
    __syncthreads();
    int blin = blockIdx.y * 8 + blockIdx.x;   // grid (8, 32): 256 blocks/batch
    if (tid == 0) {
        float t = 0.f;
#pragma unroll
        for (int w = 0; w < 8; w++) t += s_red[w];
        g_diffpart[b * 256 + blin] = t;
        __threadfence();
        unsigned old = atomicInc(&g_cnt2, NBLK - 1u);
        s_last = (old == NBLK - 1u);
    }
    __syncthreads();
    if (!s_last) return;
    __threadfence();

    // last block: diff = mean_b ||dz_b||; jax cond continues while diff>=TOL
    int w = tid >> 5, l = tid & 31;
    float t = 0.f;
    for (int i = l; i < 256; i += 32) t += g_diffpart[w * 256 + i];
#pragma unroll
    for (int o = 16; o > 0; o >>= 1) t += __shfl_down_sync(0xffffffffu, t, o);
    __shared__ float sb[8];
    if (l == 0) sb[w] = sqrtf(t);
    __syncthreads();
    if (tid == 0) {
        float mm = 0.f;
#pragma unroll
        for (int bb = 0; bb < 8; bb++) mm += sb[bb];
        mm *= 0.125f;
        if (!(mm >= TOL)) g_converged = 1;   // NaN also stops (matches jax)
    }
}

// ---------------------------------------------------------------------------
extern "C" void kernel_launch(void* const* d_in, const int* in_sizes, int n_in,
                              void* d_out, int out_size)
{
    const float* inp     = (const float*)d_in[0];
    const float* core_w1 = (const float*)d_in[1];
    const float* core_b1 = (const float*)d_in[2];
    const float* gn_w    = (const float*)d_in[3];
    const float* gn_b    = (const float*)d_in[4];
    const float* core_w2 = (const float*)d_in[5];
    const float* core_b2 = (const float*)d_in[6];
    const float* stab_w1 = (const float*)d_in[7];
    const float* stab_b1 = (const float*)d_in[8];
    const float* stab_w2 = (const float*)d_in[9];
    const float* stab_b2 = (const float*)d_in[10];
    const float* fc1_w   = (const float*)d_in[11];
    const float* fc1_b   = (const float*)d_in[12];
    const float* fc2_w   = (const float*)d_in[13];
    const float* fc2_b   = (const float*)d_in[14];
    float* out = (float*)d_out;

    dim3 blk(16, 16);
    dim3 grd(16, 16, BATCH);
    dim3 blkF(32, 8);
    dim3 grdF(8, 32, BATCH);      // 32-wide x 8-high tiles

    // fused2 is the 4th launch (ncu capture window; iter-1 normal path)
    stab1_kernel<<<grd, blk>>>(inp, stab_w1, stab_b1, fc1_w, fc1_b, fc2_w, fc2_b);
    prep_kernel<<<grd, blk>>>(inp, stab_w2, stab_b2, core_w1, core_b1);
    convz_kernel<<<grd, blk>>>(core_w1, gn_w, gn_b, 1);
    fused2_kernel<<<grdF, blkF>>>(inp, core_w2, core_b2, nullptr, 0);

    for (int it = 1; it < MAX_ITER; ++it) {
        convz_kernel<<<grd, blk>>>(core_w1, gn_w, gn_b, 1);
        fused2_kernel<<<grdF, blkF>>>(inp, core_w2, core_b2, nullptr, 0);
    }
    // final core_f (always runs): z_star -> d_out
    convz_kernel<<<grd, blk>>>(core_w1, gn_w, gn_b, 0);
    fused2_kernel<<<grdF, blkF>>>(inp, core_w2, core_b2, out, 1);
}

// round 14
// speedup vs baseline: 1.5599x; 1.1257x over previous
#include <cuda_runtime.h>
#include <cuda_bf16.h>
#include <math.h>

// ---------------------------------------------------------------------------
// MultiDEQPDEBlock: DEQ fixed-point PDE solver  (B=8, 256x256, hid=32, GN4)
// core_f: conv3x3(4->32) -> GN(4) -> GELU(erf) -> conv3x3(32->1) -> damped update
// h_fixed precomputed once; per-iter conv1 = 9-tap z conv. OVERFLOW FAST PATH:
// once a batch's GN variance overflows (all groups rstd==0) it stays overflowed
// (z grows ~x5.6/iter at the extreme pixel) -> sticky g_bfast[b]:
//   - convz skips conv + h write + stats for that batch (h unused downstream)
//   - fused2 uses constant-G dz (G = gelu(gn_b))
// All overflow paths mirror jax (var->inf, rstd->0, xn->0; NaN diff stops loop).
// ---------------------------------------------------------------------------

#define BATCH 8
#define HH 256
#define WW 256
#define PIX (HH*WW)
#define HID 32
#define SHID 16
#define GROUPS 4
#define CPG 8
#define EPS 1e-5f
#define TOL 1e-4f
#define MAX_ITER 50
#define CFL_SCALE 0.015625f
#define NBLK 2048               // 2048 blocks in iter-kernels' grids

// ---- scratch (device globals; no cudaMalloc allowed) ----
__device__ float g_h[(size_t)BATCH*HID*PIX];      // 64 MB conv1 output (pre-GN)
__device__ float g_hfix[(size_t)BATCH*HID*PIX];   // 64 MB conv of fixed channels
__device__ float g_sh[(size_t)BATCH*SHID*PIX];    // 32 MB stabilizer hidden
__device__ float g_alpha[(size_t)BATCH*PIX];
__device__ float g_z[(size_t)BATCH*PIX];
__device__ float g_gamma[BATCH];
__device__ float g_part[BATCH*256*GROUPS*2];
__device__ float g_spart[BATCH*256*4];
__device__ float g_scale[BATCH*HID];
__device__ float g_shift[BATCH*HID];
__device__ float g_diffpart[BATCH*256];
__device__ int   g_converged;
__device__ int   g_bfast[BATCH];   // sticky per-batch overflow flag
__device__ unsigned g_cnt0;     // zero-init; self-resetting via atomicInc wrap
__device__ unsigned g_cnt1;
__device__ unsigned g_cnt2;

__device__ __forceinline__ float gelu_f(float x) {
    return 0.5f * x * (1.0f + erff(x * 0.70710678118654752f));
}
__device__ __forceinline__ float sigmoid_f(float x) {
    return 1.0f / (1.0f + expf(-x));
}

// packed fp32x2 FMA (exact pairwise fp32 semantics)
#define FMA2(acc, a, bb) asm("fma.rn.f32x2 %0, %1, %2, %0;" : "+l"(acc) : "l"(a), "l"(bb))
#define UNPACK2(lo, hi, v) asm("mov.b64 {%0, %1}, %2;" : "=f"(lo), "=f"(hi) : "l"(v))

// ---------------------------------------------------------------------------
// stabilizer conv1 (3->16, GELU) + z init + spec partials; last block: gamma MLP
// ---------------------------------------------------------------------------
__global__ void __launch_bounds__(256) stab1_kernel(
    const float* __restrict__ inp, const float* __restrict__ w,
    const float* __restrict__ bias,
    const float* __restrict__ fc1_w, const float* __restrict__ fc1_b,
    const float* __restrict__ fc2_w, const float* __restrict__ fc2_b)
{
    const int b = blockIdx.z;
    const int tx0 = blockIdx.x * 16, ty0 = blockIdx.y * 16;
    __shared__ float s_in[3][18][18];
    __shared__ float s_w[27][16];
    __shared__ float s_b[16];
    __shared__ float s_red[8][4];
    __shared__ bool s_last;
    int tid = threadIdx.y * 16 + threadIdx.x;

    if (blockIdx.x == 0 && blockIdx.y == 0 && b == 0) {
        if (tid == 0) g_converged = 0;
        if (tid < BATCH) g_bfast[tid] = 0;      // graph-replay-safe reset
    }

    for (int i = tid; i < SHID * 27; i += 256) {
        int oc = i / 27, r = i % 27;
        s_w[r][oc] = w[i];
    }
    if (tid < SHID) s_b[tid] = bias[tid];

    const float* bp = inp + (size_t)b * 3 * PIX;
    for (int i = tid; i < 3 * 324; i += 256) {
        int c = i / 324, r = i % 324, yy = r / 18, xx = r % 18;
        int gy = ty0 + yy - 1, gx = tx0 + xx - 1;
        float v = 0.f;
        if ((unsigned)gy < 256u && (unsigned)gx < 256u)
            v = bp[c * PIX + gy * WW + gx];
        s_in[c][yy][xx] = v;
    }
    __syncthreads();

    int ty = threadIdx.y, tx = threadIdx.x;
    float in[27];
#pragma unroll
    for (int c = 0; c < 3; c++)
#pragma unroll
        for (int ky = 0; ky < 3; ky++)
#pragma unroll
            for (int kx = 0; kx < 3; kx++)
                in[c * 9 + ky * 3 + kx] = s_in[c][ty + ky][tx + kx];

    float acc[SHID];
#pragma unroll
    for (int oc = 0; oc < SHID; oc++) acc[oc] = s_b[oc];
#pragma unroll
    for (int r = 0; r < 27; r++) {
        float iv = in[r];
#pragma unroll
        for (int oc = 0; oc < SHID; oc++) acc[oc] += iv * s_w[r][oc];
    }

    int pix = (ty0 + ty) * WW + (tx0 + tx);
    float* out = g_sh + (size_t)b * SHID * PIX + pix;
#pragma unroll
    for (int oc = 0; oc < SHID; oc++)
        out[oc * PIX] = gelu_f(acc[oc]);

    // z init (channel 0 = boundary)
    g_z[b * PIX + pix] = s_in[0][ty + 1][tx + 1];

    // spec partials: |boundary| and k stats
    float bv = fabsf(s_in[0][ty + 1][tx + 1]);
    float kv = s_in[2][ty + 1][tx + 1];
    float s1 = bv, q1 = bv * bv, s2 = kv, q2 = kv * kv;
#pragma unroll
    for (int o = 16; o > 0; o >>= 1) {
        s1 += __shfl_down_sync(0xffffffffu, s1, o);
        q1 += __shfl_down_sync(0xffffffffu, q1, o);
        s2 += __shfl_down_sync(0xffffffffu, s2, o);
        q2 += __shfl_down_sync(0xffffffffu, q2, o);
    }
    int lane = tid & 31, warp = tid >> 5;
    if (lane == 0) { s_red[warp][0] = s1; s_red[warp][1] = q1; s_red[warp][2] = s2; s_red[warp][3] = q2; }
    __syncthreads();
    int blin = blockIdx.y * 16 + blockIdx.x;
    if (tid < 4) {
        float v = 0.f;
#pragma unroll
        for (int w8 = 0; w8 < 8; w8++) v += s_red[w8][tid];
        g_spart[(b * 256 + blin) * 4 + tid] = v;
        __threadfence();
    }
    __syncthreads();
    if (tid == 0) {
        unsigned old = atomicInc(&g_cnt0, NBLK - 1u);
        s_last = (old == NBLK - 1u);
    }
    __syncthreads();
    if (!s_last) return;
    __threadfence();

    // last block: per-batch spec_ctrl MLP -> gamma (warp w = batch w)
    int w8 = tid >> 5, l = tid & 31;
    float S1 = 0, Q1 = 0, S2 = 0, Q2 = 0;
    for (int i = l; i < 256; i += 32) {
        S1 += g_spart[(w8 * 256 + i) * 4 + 0];
        Q1 += g_spart[(w8 * 256 + i) * 4 + 1];
        S2 += g_spart[(w8 * 256 + i) * 4 + 2];
        Q2 += g_spart[(w8 * 256 + i) * 4 + 3];
    }
#pragma unroll
    for (int o = 16; o > 0; o >>= 1) {
        S1 += __shfl_down_sync(0xffffffffu, S1, o);
        Q1 += __shfl_down_sync(0xffffffffu, Q1, o);
        S2 += __shfl_down_sync(0xffffffffu, S2, o);
        Q2 += __shfl_down_sync(0xffffffffu, Q2, o);
    }
    if (l == 0) {
        const float N = (float)PIX;
        float m1 = S1 / N, m2 = S2 / N;
        float v1 = (Q1 - N * m1 * m1) / (N - 1.0f);
        float v2 = (Q2 - N * m2 * m2) / (N - 1.0f);
        float feat[5] = { m1, sqrtf(fmaxf(v1, 0.f)), m2, sqrtf(fmaxf(v2, 0.f)), 1.0f };
        float outv = fc2_b[0];
        for (int j = 0; j < 32; j++) {
            float t = fc1_b[j];
#pragma unroll
            for (int i = 0; i < 5; i++) t += feat[i] * fc1_w[j * 5 + i];
            outv += gelu_f(t) * fc2_w[j];
        }
        g_gamma[w8] = (0.5f + 1.5f * sigmoid_f(outv)) * CFL_SCALE;
    }
}

// ---------------------------------------------------------------------------
// prep: stab2 (16->1 sigmoid -> alpha)  AND  hfix (conv3x3 of [b,m,k] + bias)
// ---------------------------------------------------------------------------
__global__ void __launch_bounds__(256) prep_kernel(
    const float* __restrict__ inp,
    const float* __restrict__ w2s, const float* __restrict__ b2s,
    const float* __restrict__ w1, const float* __restrict__ b1)
{
    const int b = blockIdx.z;
    const int tx0 = blockIdx.x * 16, ty0 = blockIdx.y * 16;
    __shared__ float s_sh[SHID][18][18];
    __shared__ float s_in[3][18][18];
    __shared__ float s_ws[SHID * 9];
    __shared__ __align__(16) float s_wh[27][32];
    __shared__ float s_bh[32];
    int tid = threadIdx.y * 16 + threadIdx.x;

    if (tid < SHID * 9) s_ws[tid] = w2s[tid];
    for (int i = tid; i < HID * 27; i += 256) {
        int oc = i / 27, r = i % 27;
        s_wh[r][oc] = w1[oc * 36 + 9 + r];   // skip z-channel taps
    }
    if (tid < HID) s_bh[tid] = b1[tid];

    const float* hp = g_sh + (size_t)b * SHID * PIX;
    for (int i = tid; i < SHID * 324; i += 256) {
        int c = i / 324, r = i % 324, yy = r / 18, xx = r % 18;
        int gy = ty0 + yy - 1, gx = tx0 + xx - 1;
        float v = 0.f;
        if ((unsigned)gy < 256u && (unsigned)gx < 256u)
            v = hp[c * PIX + gy * WW + gx];
        s_sh[c][yy][xx] = v;
    }
    const float* bp = inp + (size_t)b * 3 * PIX;
    for (int i = tid; i < 3 * 324; i += 256) {
        int c = i / 324, r = i % 324, yy = r / 18, xx = r % 18;
        int gy = ty0 + yy - 1, gx = tx0 + xx - 1;
        float v = 0.f;
        if ((unsigned)gy < 256u && (unsigned)gx < 256u)
            v = bp[c * PIX + gy * WW + gx];
        s_in[c][yy][xx] = v;
    }
    __syncthreads();

    int ty = threadIdx.y, tx = threadIdx.x;
    int pix = (ty0 + ty) * WW + (tx0 + tx);

    // stab2: alpha
    {
        float acc = b2s[0];
#pragma unroll
        for (int c = 0; c < SHID; c++)
#pragma unroll
            for (int ky = 0; ky < 3; ky++)
#pragma unroll
                for (int kx = 0; kx < 3; kx++)
                    acc += s_ws[c * 9 + ky * 3 + kx] * s_sh[c][ty + ky][tx + kx];
        g_alpha[(size_t)b * PIX + pix] = sigmoid_f(acc);
    }

    // hfix: 27-tap conv of fixed channels into 32 outputs
    {
        float acc[HID];
#pragma unroll
        for (int oc = 0; oc < HID; oc++) acc[oc] = s_bh[oc];
#pragma unroll
        for (int c = 0; c < 3; c++)
#pragma unroll
            for (int ky = 0; ky < 3; ky++)
#pragma unroll
                for (int kx = 0; kx < 3; kx++) {
                    float iv = s_in[c][ty + ky][tx + kx];
                    int r = c * 9 + ky * 3 + kx;
#pragma unroll
                    for (int j = 0; j < 8; j++) {
                        float4 w4 = ((const float4*)&s_wh[r][0])[j];
                        acc[4*j+0] += iv * w4.x; acc[4*j+1] += iv * w4.y;
                        acc[4*j+2] += iv * w4.z; acc[4*j+3] += iv * w4.w;
                    }
                }
        float* op = g_hfix + (size_t)b * HID * PIX + pix;
#pragma unroll
        for (int oc = 0; oc < HID; oc++) op[oc * PIX] = acc[oc];
    }
}

// ---------------------------------------------------------------------------
// convz: h = h_fixed + conv3x3(z, w1[:,0]) + GN partials; LAST BLOCK folds
// stats. Batches with g_bfast set skip everything (h unused; scale/shift
// frozen at overflow values). Fold sets g_bfast when all 4 groups rstd==0.
// ---------------------------------------------------------------------------
__global__ void __launch_bounds__(256, 4) convz_kernel(
    const float* __restrict__ w1, const float* __restrict__ gn_w,
    const float* __restrict__ gn_b, int check)
{
    if (check && g_converged) return;
    const int b = blockIdx.z;
    const int tx0 = blockIdx.x * 16, ty0 = blockIdx.y * 16;
    __shared__ float s_z[18][18];
    __shared__ __align__(16) float s_w[9][32];
    __shared__ float s_red[8][8];
    __shared__ int s_rz[32];
    __shared__ bool s_last;
    __shared__ bool s_bf;
    int tid = threadIdx.y * 16 + threadIdx.x;

    if (tid == 0) s_bf = (g_bfast[b] != 0);
    __syncthreads();

    if (!s_bf) {
        for (int i = tid; i < HID * 9; i += 256) {
            int oc = i / 9, r = i % 9;
            s_w[r][oc] = w1[oc * 36 + r];       // z-channel taps (c=0)
        }

        const float* zp = g_z + b * PIX;
        for (int i = tid; i < 324; i += 256) {
            int yy = i / 18, xx = i % 18;
            int gy = ty0 + yy - 1, gx = tx0 + xx - 1;
            float v = 0.f;
            if ((unsigned)gy < 256u && (unsigned)gx < 256u)
                v = zp[gy * WW + gx];
            s_z[yy][xx] = v;
        }
        __syncthreads();

        int ty = threadIdx.y, tx = threadIdx.x;
        float zv[9];
#pragma unroll
        for (int ky = 0; ky < 3; ky++)
#pragma unroll
            for (int kx = 0; kx < 3; kx++)
                zv[ky * 3 + kx] = s_z[ty + ky][tx + kx];

        int pix = (ty0 + ty) * WW + (tx0 + tx);
        const float* fp = g_hfix + (size_t)b * HID * PIX + pix;
        float acc[HID];
#pragma unroll
        for (int oc = 0; oc < HID; oc++) acc[oc] = fp[oc * PIX];
#pragma unroll
        for (int r = 0; r < 9; r++) {
            float iv = zv[r];
#pragma unroll
            for (int j = 0; j < 8; j++) {
                float4 w4 = ((const float4*)&s_w[r][0])[j];
                acc[4*j+0] += iv * w4.x; acc[4*j+1] += iv * w4.y;
                acc[4*j+2] += iv * w4.z; acc[4*j+3] += iv * w4.w;
            }
        }

        float* hp = g_h + (size_t)b * HID * PIX + pix;
        float gs[4] = {0, 0, 0, 0}, gq[4] = {0, 0, 0, 0};
#pragma unroll
        for (int oc = 0; oc < HID; oc++) {
            float v = acc[oc];
            hp[oc * PIX] = v;
            gs[oc >> 3] += v;
            gq[oc >> 3] += v * v;
        }
#pragma unroll
        for (int o = 16; o > 0; o >>= 1) {
#pragma unroll
            for (int g = 0; g < 4; g++) {
                gs[g] += __shfl_down_sync(0xffffffffu, gs[g], o);
                gq[g] += __shfl_down_sync(0xffffffffu, gq[g], o);
            }
        }
        int lane = tid & 31, warp = tid >> 5;
        if (lane == 0) {
#pragma unroll
            for (int g = 0; g < 4; g++) { s_red[warp][g] = gs[g]; s_red[warp][4 + g] = gq[g]; }
        }
        __syncthreads();
        int blin = blockIdx.y * 16 + blockIdx.x;
        if (tid < 8) {
            float v = 0.f;
#pragma unroll
            for (int w = 0; w < 8; w++) v += s_red[w][tid];
            int g = tid & 3, which = tid >> 2;
            g_part[((b * 256 + blin) * 4 + g) * 2 + which] = v;
            __threadfence();
        }
        __syncthreads();
    }

    if (tid == 0) {
        unsigned old = atomicInc(&g_cnt1, NBLK - 1u);
        s_last = (old == NBLK - 1u);
    }
    __syncthreads();
    if (!s_last) return;
    __threadfence();

    // last block: fold GN stats for all 32 (b,g) pairs; 8 lanes per pair.
    // bb == warp id, so the g_bfast guard is warp-uniform.
    int pair = tid >> 3, l8 = tid & 7;
    int bb = pair >> 2, g = pair & 3;
    if (g_bfast[bb] == 0) {
        float s = 0.f, q = 0.f;
        for (int i = l8; i < 256; i += 8) {
            s += g_part[((bb * 256 + i) * 4 + g) * 2 + 0];
            q += g_part[((bb * 256 + i) * 4 + g) * 2 + 1];
        }
#pragma unroll
        for (int o = 4; o > 0; o >>= 1) {
            s += __shfl_down_sync(0xffffffffu, s, o, 8);
            q += __shfl_down_sync(0xffffffffu, q, o, 8);
        }
        if (l8 == 0) {
            const float invN = 1.0f / (float)(CPG * PIX);
            float mean = s * invN;
            float Qn = q * invN;
            float var = isinf(Qn) ? Qn : fmaxf(Qn - mean * mean, 0.0f);
            float rstd = rsqrtf(var + EPS);       // var=inf -> rstd=0
#pragma unroll
            for (int c = 0; c < CPG; c++) {
                int gc = g * CPG + c;
                float sc = gn_w[gc] * rstd;
                g_scale[bb * HID + gc] = sc;
                g_shift[bb * HID + gc] = (rstd == 0.0f) ? gn_b[gc] : (gn_b[gc] - mean * sc);
            }
            s_rz[pair] = (rstd == 0.0f);
        }
    } else if (l8 == 0) {
        s_rz[pair] = 1;                           // already fast: stays fast
    }
    __syncthreads();
    if (tid < BATCH) {
        if (s_rz[tid * 4 + 0] && s_rz[tid * 4 + 1] &&
            s_rz[tid * 4 + 2] && s_rz[tid * 4 + 3])
            g_bfast[tid] = 1;                     // sticky
    }
}

// ---------------------------------------------------------------------------
// fused2: GN->GELU->conv2(32->1)->damped update; LAST BLOCK folds diff.
// Tile 32x8, channel-PAIRED s_h + fma.rn.f32x2 conv loop.
// Normal path FILL8 staging; FAST path (all sc==0) = constant-dz shortcut.
// ---------------------------------------------------------------------------
// fill one halo pixel (yy,xx) for channels [base, base+8) into paired layout
#define FILL8(base, yy, xx, inb, hb)                                       \
    {                                                                      \
        float hv[8];                                                       \
        _Pragma("unroll")                                                  \
        for (int c = 0; c < 8; c++)                                        \
            hv[c] = (inb) ? (hb)[(base + c) * PIX] : 0.f;                  \
        _Pragma("unroll")                                                  \
        for (int c = 0; c < 8; c++) {                                      \
            float sc = s_sc[base + c];                                     \
            float t = (sc == 0.0f) ? s_sf[base + c]                        \
                                   : (hv[c] * sc + s_sf[base + c]);        \
            s_h[(base + c) >> 1][yy][xx][(base + c) & 1] =                 \
                (inb) ? gelu_f(t) : 0.f;                                   \
        }                                                                  \
    }

__global__ void __launch_bounds__(256, 3) fused2_kernel(
    const float* __restrict__ inp, const float* __restrict__ w2,
    const float* __restrict__ b2, float* __restrict__ final_out, int mode)
{
    if (mode == 0 && g_converged) return;
    const int b = blockIdx.z;
    const int tx0 = blockIdx.x * 32, ty0 = blockIdx.y * 8;
    __shared__ __align__(8) float s_h[16][10][34][2];   // channel-paired
    __shared__ __align__(8) float s_wp[9][16][2];       // [pos][c2][elem]
    __shared__ float s_sc[HID], s_sf[HID];
    __shared__ float s_G[HID];
    __shared__ float s_red[8];
    __shared__ float s_Dfull;
    __shared__ bool s_fast;
    __shared__ bool s_last;
    int tid = threadIdx.y * 32 + threadIdx.x;

    for (int i = tid; i < HID * 9; i += 256) {
        int c = i / 9, pos = i % 9;
        s_wp[pos][c >> 1][c & 1] = w2[i];
    }
    if (tid < HID) { s_sc[tid] = g_scale[b * HID + tid]; s_sf[tid] = g_shift[b * HID + tid]; }
    __syncthreads();

    // warp 0: overflow fast-path detection + constant-G precompute
    if (tid < 32) {
        int zero = (s_sc[tid] == 0.0f);
        unsigned bal = __ballot_sync(0xffffffffu, zero);
        float wsum = 0.f;
#pragma unroll
        for (int j = 0; j < 9; j++) wsum += s_wp[j][tid >> 1][tid & 1];
        float Gc = gelu_f(s_sf[tid]);     // == gelu(gn_b) when sc==0
        s_G[tid] = Gc;
        float t = Gc * wsum;
#pragma unroll
        for (int o = 16; o > 0; o >>= 1) t += __shfl_down_sync(0xffffffffu, t, o);
        if (tid == 0) { s_fast = (bal == 0xffffffffu); s_Dfull = t; }
    }
    __syncthreads();

    int ty = threadIdx.y, tx = threadIdx.x;
    float acc;

    if (s_fast) {
        // all sc==0: G constant per channel; dz depends only on valid-tap mask
        int Y = ty0 + ty, X = tx0 + tx;
        bool interior = (Y >= 1) && (Y <= 254) && (X >= 1) && (X <= 254);
        if (interior) {
            acc = b2[0] + s_Dfull;
        } else {
            acc = b2[0];
            int ky0 = (Y == 0) ? 1 : 0, ky1 = (Y == 255) ? 2 : 3;
            int kx0 = (X == 0) ? 1 : 0, kx1 = (X == 255) ? 2 : 3;
            for (int c = 0; c < HID; c++) {
                float wsum = 0.f;
                for (int ky = ky0; ky < ky1; ky++)
                    for (int kx = kx0; kx < kx1; kx++)
                        wsum += s_wp[ky * 3 + kx][c >> 1][c & 1];
                acc += s_G[c] * wsum;
            }
        }
    } else {
        const float* hp = g_h + (size_t)b * HID * PIX;
        {
            // halo = 10 rows x 34 cols = 340 pixels
            // pixel 1: p = tid (tid < 340 always)
            int yy = tid / 34, xx = tid % 34;
            int gy = ty0 + yy - 1, gx = tx0 + xx - 1;
            bool inb = ((unsigned)gy < 256u) && ((unsigned)gx < 256u);
            const float* hb = hp + (inb ? (gy * WW + gx) : 0);
            FILL8(0, yy, xx, inb, hb)
            FILL8(8, yy, xx, inb, hb)
            FILL8(16, yy, xx, inb, hb)
            FILL8(24, yy, xx, inb, hb)
            // pixel 2: p = tid + 256 (only tid < 84)
            if (tid < 84) {
                int p2 = tid + 256;
                int yy2 = p2 / 34, xx2 = p2 % 34;
                int gy2 = ty0 + yy2 - 1, gx2 = tx0 + xx2 - 1;
                bool inb2 = ((unsigned)gy2 < 256u) && ((unsigned)gx2 < 256u);
                const float* hb2 = hp + (inb2 ? (gy2 * WW + gx2) : 0);
                FILL8(0, yy2, xx2, inb2, hb2)
                FILL8(8, yy2, xx2, inb2, hb2)
                FILL8(16, yy2, xx2, inb2, hb2)
                FILL8(24, yy2, xx2, inb2, hb2)
            }
        }
        __syncthreads();

        // channel-paired conv: 144 LDS.64 + 144 bcast LDS.64 + 144 FFMA2
        unsigned long long pa[4] = {0ull, 0ull, 0ull, 0ull};
#pragma unroll
        for (int c2 = 0; c2 < 16; c2++) {
#pragma unroll
            for (int ky = 0; ky < 3; ky++)
#pragma unroll
                for (int kx = 0; kx < 3; kx++) {
                    int pos = ky * 3 + kx;
                    unsigned long long h2 =
                        *(const unsigned long long*)&s_h[c2][ty + ky][tx + kx][0];
                    unsigned long long w2p =
                        *(const unsigned long long*)&s_wp[pos][c2][0];
                    FMA2(pa[(c2 * 9 + pos) & 3], h2, w2p);
                }
        }
        float lo0, hi0, lo1, hi1, lo2, hi2, lo3, hi3;
        UNPACK2(lo0, hi0, pa[0]);
        UNPACK2(lo1, hi1, pa[1]);
        UNPACK2(lo2, hi2, pa[2]);
        UNPACK2(lo3, hi3, pa[3]);
        acc = b2[0] + (((lo0 + hi0) + (lo1 + hi1)) + ((lo2 + hi2) + (lo3 + hi3)));
    }

    int pix = (ty0 + ty) * WW + (tx0 + tx);
    int off = b * PIX + pix;
    const float* bp = inp + (size_t)b * 3 * PIX;
    float zold = g_z[off];
    // mirror XLA elementwise rounding exactly (no FMA contraction)
    float ga   = __fmul_rn(g_gamma[b], g_alpha[off]);
    float znew = __fadd_rn(zold, __fmul_rn(ga, acc));
    float m  = bp[PIX + pix];
    float bv = bp[pix];
    float res = __fadd_rn(__fmul_rn(znew, __fadd_rn(1.0f, -m)), __fmul_rn(bv, m));

    if (mode != 0) { final_out[off] = res; return; }

    g_z[off] = res;
    float d = __fadd_rn(res, -zold);
    float s = d * d;
#pragma unroll
    for (int o = 16; o > 0; o >>= 1) s += __shfl_down_sync(0xffffffffu, s, o);
    int lane = tid & 31, warp = tid >> 5;
    if (lane == 0) s_red[warp] = s;
    __syncthreads();
    int blin = blockIdx.y * 8 + blockIdx.x;   // grid (8, 32): 256 blocks/batch
    if (tid == 0) {
        float t = 0.f;
#pragma unroll
        for (int w = 0; w < 8; w++) t += s_red[w];
        g_diffpart[b * 256 + blin] = t;
        __threadfence();
        unsigned old = atomicInc(&g_cnt2, NBLK - 1u);
        s_last = (old == NBLK - 1u);
    }
    __syncthreads();
    if (!s_last) return;
    __threadfence();

    // last block: diff = mean_b ||dz_b||; jax cond continues while diff>=TOL
    int w = tid >> 5, l = tid & 31;
    float t = 0.f;
    for (int i = l; i < 256; i += 32) t += g_diffpart[w * 256 + i];
#pragma unroll
    for (int o = 16; o > 0; o >>= 1) t += __shfl_down_sync(0xffffffffu, t, o);
    __shared__ float sb[8];
    if (l == 0) sb[w] = sqrtf(t);
    __syncthreads();
    if (tid == 0) {
        float mm = 0.f;
#pragma unroll
        for (int bb = 0; bb < 8; bb++) mm += sb[bb];
        mm *= 0.125f;
        if (!(mm >= TOL)) g_converged = 1;   // NaN also stops (matches jax)
    }
}

// ---------------------------------------------------------------------------
extern "C" void kernel_launch(void* const* d_in, const int* in_sizes, int n_in,
                              void* d_out, int out_size)
{
    const float* inp     = (const float*)d_in[0];
    const float* core_w1 = (const float*)d_in[1];
    const float* core_b1 = (const float*)d_in[2];
    const float* gn_w    = (const float*)d_in[3];
    const float* gn_b    = (const float*)d_in[4];
    const float* core_w2 = (const float*)d_in[5];
    const float* core_b2 = (const float*)d_in[6];
    const float* stab_w1 = (const float*)d_in[7];
    const float* stab_b1 = (const float*)d_in[8];
    const float* stab_w2 = (const float*)d_in[9];
    const float* stab_b2 = (const float*)d_in[10];
    const float* fc1_w   = (const float*)d_in[11];
    const float* fc1_b   = (const float*)d_in[12];
    const float* fc2_w   = (const float*)d_in[13];
    const float* fc2_b   = (const float*)d_in[14];
    float* out = (float*)d_out;

    dim3 blk(16, 16);
    dim3 grd(16, 16, BATCH);
    dim3 blkF(32, 8);
    dim3 grdF(8, 32, BATCH);      // 32-wide x 8-high tiles

    // fused2 is the 4th launch (ncu capture window; iter-1 normal path)
    stab1_kernel<<<grd, blk>>>(inp, stab_w1, stab_b1, fc1_w, fc1_b, fc2_w, fc2_b);
    prep_kernel<<<grd, blk>>>(inp, stab_w2, stab_b2, core_w1, core_b1);
    convz_kernel<<<grd, blk>>>(core_w1, gn_w, gn_b, 1);
    fused2_kernel<<<grdF, blkF>>>(inp, core_w2, core_b2, nullptr, 0);

    for (int it = 1; it < MAX_ITER; ++it) {
        convz_kernel<<<grd, blk>>>(core_w1, gn_w, gn_b, 1);
        fused2_kernel<<<grdF, blkF>>>(inp, core_w2, core_b2, nullptr, 0);
    }
    // final core_f (always runs): z_star -> d_out
    convz_kernel<<<grd, blk>>>(core_w1, gn_w, gn_b, 0);
    fused2_kernel<<<grdF, blkF>>>(inp, core_w2, core_b2, out, 1);
}

// round 16
// speedup vs baseline: 1.6100x; 1.0321x over previous
#include <cuda_runtime.h>
#include <cuda_bf16.h>
#include <math.h>

// ---------------------------------------------------------------------------
// MultiDEQPDEBlock: DEQ fixed-point PDE solver  (B=8, 256x256, hid=32, GN4)
// core_f: conv3x3(4->32) -> GN(4) -> GELU(erf) -> conv3x3(32->1) -> damped update
// h_fixed precomputed once; per-iter conv1 = 9-tap z conv, VECTORIZED:
// 4 px/thread, float4 hfix reads + h writes (tile 64x16, 512 blocks).
// OVERFLOW FAST PATH: once a batch's GN variance overflows it stays overflowed
// -> sticky g_bfast[b]: convz skips batch entirely; fused2 uses constant-G dz.
// All overflow paths mirror jax (var->inf, rstd->0, xn->0; NaN diff stops loop).
// ---------------------------------------------------------------------------

#define BATCH 8
#define HH 256
#define WW 256
#define PIX (HH*WW)
#define HID 32
#define SHID 16
#define GROUPS 4
#define CPG 8
#define EPS 1e-5f
#define TOL 1e-4f
#define MAX_ITER 50
#define CFL_SCALE 0.015625f
#define NBLK   2048             // stab1 / fused2 grids
#define NBLK_Z 512              // convz grid (4,16,8)
#define NBZ    64               // convz blocks per batch

// ---- scratch (device globals; no cudaMalloc allowed) ----
__device__ float g_h[(size_t)BATCH*HID*PIX];      // 64 MB conv1 output (pre-GN)
__device__ float g_hfix[(size_t)BATCH*HID*PIX];   // 64 MB conv of fixed channels
__device__ float g_sh[(size_t)BATCH*SHID*PIX];    // 32 MB stabilizer hidden
__device__ float g_alpha[(size_t)BATCH*PIX];
__device__ float g_z[(size_t)BATCH*PIX];
__device__ float g_gamma[BATCH];
__device__ float g_part[BATCH*256*GROUPS*2];
__device__ float g_spart[BATCH*256*4];
__device__ float g_scale[BATCH*HID];
__device__ float g_shift[BATCH*HID];
__device__ float g_diffpart[BATCH*256];
__device__ int   g_converged;
__device__ int   g_bfast[BATCH];   // sticky per-batch overflow flag
__device__ unsigned g_cnt0;     // zero-init; self-resetting via atomicInc wrap
__device__ unsigned g_cnt1;
__device__ unsigned g_cnt2;

__device__ __forceinline__ float gelu_f(float x) {
    return 0.5f * x * (1.0f + erff(x * 0.70710678118654752f));
}
__device__ __forceinline__ float sigmoid_f(float x) {
    return 1.0f / (1.0f + expf(-x));
}

// packed fp32x2 FMA (exact pairwise fp32 semantics)
#define FMA2(acc, a, bb) asm("fma.rn.f32x2 %0, %1, %2, %0;" : "+l"(acc) : "l"(a), "l"(bb))
#define UNPACK2(lo, hi, v) asm("mov.b64 {%0, %1}, %2;" : "=f"(lo), "=f"(hi) : "l"(v))

// ---------------------------------------------------------------------------
// stabilizer conv1 (3->16, GELU) + z init + spec partials; last block: gamma MLP
// ---------------------------------------------------------------------------
__global__ void __launch_bounds__(256) stab1_kernel(
    const float* __restrict__ inp, const float* __restrict__ w,
    const float* __restrict__ bias,
    const float* __restrict__ fc1_w, const float* __restrict__ fc1_b,
    const float* __restrict__ fc2_w, const float* __restrict__ fc2_b)
{
    const int b = blockIdx.z;
    const int tx0 = blockIdx.x * 16, ty0 = blockIdx.y * 16;
    __shared__ float s_in[3][18][18];
    __shared__ float s_w[27][16];
    __shared__ float s_b[16];
    __shared__ float s_red[8][4];
    __shared__ bool s_last;
    int tid = threadIdx.y * 16 + threadIdx.x;

    if (blockIdx.x == 0 && blockIdx.y == 0 && b == 0) {
        if (tid == 0) g_converged = 0;
        if (tid < BATCH) g_bfast[tid] = 0;      // graph-replay-safe reset
    }

    for (int i = tid; i < SHID * 27; i += 256) {
        int oc = i / 27, r = i % 27;
        s_w[r][oc] = w[i];
    }
    if (tid < SHID) s_b[tid] = bias[tid];

    const float* bp = inp + (size_t)b * 3 * PIX;
    for (int i = tid; i < 3 * 324; i += 256) {
        int c = i / 324, r = i % 324, yy = r / 18, xx = r % 18;
        int gy = ty0 + yy - 1, gx = tx0 + xx - 1;
        float v = 0.f;
        if ((unsigned)gy < 256u && (unsigned)gx < 256u)
            v = bp[c * PIX + gy * WW + gx];
        s_in[c][yy][xx] = v;
    }
    __syncthreads();

    int ty = threadIdx.y, tx = threadIdx.x;
    float in[27];
#pragma unroll
    for (int c = 0; c < 3; c++)
#pragma unroll
        for (int ky = 0; ky < 3; ky++)
#pragma unroll
            for (int kx = 0; kx < 3; kx++)
                in[c * 9 + ky * 3 + kx] = s_in[c][ty + ky][tx + kx];

    float acc[SHID];
#pragma unroll
    for (int oc = 0; oc < SHID; oc++) acc[oc] = s_b[oc];
#pragma unroll
    for (int r = 0; r < 27; r++) {
        float iv = in[r];
#pragma unroll
        for (int oc = 0; oc < SHID; oc++) acc[oc] += iv * s_w[r][oc];
    }

    int pix = (ty0 + ty) * WW + (tx0 + tx);
    float* out = g_sh + (size_t)b * SHID * PIX + pix;
#pragma unroll
    for (int oc = 0; oc < SHID; oc++)
        out[oc * PIX] = gelu_f(acc[oc]);

    // z init (channel 0 = boundary)
    g_z[b * PIX + pix] = s_in[0][ty + 1][tx + 1];

    // spec partials: |boundary| and k stats
    float bv = fabsf(s_in[0][ty + 1][tx + 1]);
    float kv = s_in[2][ty + 1][tx + 1];
    float s1 = bv, q1 = bv * bv, s2 = kv, q2 = kv * kv;
#pragma unroll
    for (int o = 16; o > 0; o >>= 1) {
        s1 += __shfl_down_sync(0xffffffffu, s1, o);
        q1 += __shfl_down_sync(0xffffffffu, q1, o);
        s2 += __shfl_down_sync(0xffffffffu, s2, o);
        q2 += __shfl_down_sync(0xffffffffu, q2, o);
    }
    int lane = tid & 31, warp = tid >> 5;
    if (lane == 0) { s_red[warp][0] = s1; s_red[warp][1] = q1; s_red[warp][2] = s2; s_red[warp][3] = q2; }
    __syncthreads();
    int blin = blockIdx.y * 16 + blockIdx.x;
    if (tid < 4) {
        float v = 0.f;
#pragma unroll
        for (int w8 = 0; w8 < 8; w8++) v += s_red[w8][tid];
        g_spart[(b * 256 + blin) * 4 + tid] = v;
        __threadfence();
    }
    __syncthreads();
    if (tid == 0) {
        unsigned old = atomicInc(&g_cnt0, NBLK - 1u);
        s_last = (old == NBLK - 1u);
    }
    __syncthreads();
    if (!s_last) return;
    __threadfence();

    // last block: per-batch spec_ctrl MLP -> gamma (warp w = batch w)
    int w8 = tid >> 5, l = tid & 31;
    float S1 = 0, Q1 = 0, S2 = 0, Q2 = 0;
    for (int i = l; i < 256; i += 32) {
        S1 += g_spart[(w8 * 256 + i) * 4 + 0];
        Q1 += g_spart[(w8 * 256 + i) * 4 + 1];
        S2 += g_spart[(w8 * 256 + i) * 4 + 2];
        Q2 += g_spart[(w8 * 256 + i) * 4 + 3];
    }
#pragma unroll
    for (int o = 16; o > 0; o >>= 1) {
        S1 += __shfl_down_sync(0xffffffffu, S1, o);
        Q1 += __shfl_down_sync(0xffffffffu, Q1, o);
        S2 += __shfl_down_sync(0xffffffffu, S2, o);
        Q2 += __shfl_down_sync(0xffffffffu, Q2, o);
    }
    if (l == 0) {
        const float N = (float)PIX;
        float m1 = S1 / N, m2 = S2 / N;
        float v1 = (Q1 - N * m1 * m1) / (N - 1.0f);
        float v2 = (Q2 - N * m2 * m2) / (N - 1.0f);
        float feat[5] = { m1, sqrtf(fmaxf(v1, 0.f)), m2, sqrtf(fmaxf(v2, 0.f)), 1.0f };
        float outv = fc2_b[0];
        for (int j = 0; j < 32; j++) {
            float t = fc1_b[j];
#pragma unroll
            for (int i = 0; i < 5; i++) t += feat[i] * fc1_w[j * 5 + i];
            outv += gelu_f(t) * fc2_w[j];
        }
        g_gamma[w8] = (0.5f + 1.5f * sigmoid_f(outv)) * CFL_SCALE;
    }
}

// ---------------------------------------------------------------------------
// prep: stab2 (16->1 sigmoid -> alpha)  AND  hfix (conv3x3 of [b,m,k] + bias)
// ---------------------------------------------------------------------------
__global__ void __launch_bounds__(256) prep_kernel(
    const float* __restrict__ inp,
    const float* __restrict__ w2s, const float* __restrict__ b2s,
    const float* __restrict__ w1, const float* __restrict__ b1)
{
    const int b = blockIdx.z;
    const int tx0 = blockIdx.x * 16, ty0 = blockIdx.y * 16;
    __shared__ float s_sh[SHID][18][18];
    __shared__ float s_in[3][18][18];
    __shared__ float s_ws[SHID * 9];
    __shared__ __align__(16) float s_wh[27][32];
    __shared__ float s_bh[32];
    int tid = threadIdx.y * 16 + threadIdx.x;

    if (tid < SHID * 9) s_ws[tid] = w2s[tid];
    for (int i = tid; i < HID * 27; i += 256) {
        int oc = i / 27, r = i % 27;
        s_wh[r][oc] = w1[oc * 36 + 9 + r];   // skip z-channel taps
    }
    if (tid < HID) s_bh[tid] = b1[tid];

    const float* hp = g_sh + (size_t)b * SHID * PIX;
    for (int i = tid; i < SHID * 324; i += 256) {
        int c = i / 324, r = i % 324, yy = r / 18, xx = r % 18;
        int gy = ty0 + yy - 1, gx = tx0 + xx - 1;
        float v = 0.f;
        if ((unsigned)gy < 256u && (unsigned)gx < 256u)
            v = hp[c * PIX + gy * WW + gx];
        s_sh[c][yy][xx] = v;
    }
    const float* bp = inp + (size_t)b * 3 * PIX;
    for (int i = tid; i < 3 * 324; i += 256) {
        int c = i / 324, r = i % 324, yy = r / 18, xx = r % 18;
        int gy = ty0 + yy - 1, gx = tx0 + xx - 1;
        float v = 0.f;
        if ((unsigned)gy < 256u && (unsigned)gx < 256u)
            v = bp[c * PIX + gy * WW + gx];
        s_in[c][yy][xx] = v;
    }
    __syncthreads();

    int ty = threadIdx.y, tx = threadIdx.x;
    int pix = (ty0 + ty) * WW + (tx0 + tx);

    // stab2: alpha
    {
        float acc = b2s[0];
#pragma unroll
        for (int c = 0; c < SHID; c++)
#pragma unroll
            for (int ky = 0; ky < 3; ky++)
#pragma unroll
                for (int kx = 0; kx < 3; kx++)
                    acc += s_ws[c * 9 + ky * 3 + kx] * s_sh[c][ty + ky][tx + kx];
        g_alpha[(size_t)b * PIX + pix] = sigmoid_f(acc);
    }

    // hfix: 27-tap conv of fixed channels into 32 outputs
    {
        float acc[HID];
#pragma unroll
        for (int oc = 0; oc < HID; oc++) acc[oc] = s_bh[oc];
#pragma unroll
        for (int c = 0; c < 3; c++)
#pragma unroll
            for (int ky = 0; ky < 3; ky++)
#pragma unroll
                for (int kx = 0; kx < 3; kx++) {
                    float iv = s_in[c][ty + ky][tx + kx];
                    int r = c * 9 + ky * 3 + kx;
#pragma unroll
                    for (int j = 0; j < 8; j++) {
                        float4 w4 = ((const float4*)&s_wh[r][0])[j];
                        acc[4*j+0] += iv * w4.x; acc[4*j+1] += iv * w4.y;
                        acc[4*j+2] += iv * w4.z; acc[4*j+3] += iv * w4.w;
                    }
                }
        float* op = g_hfix + (size_t)b * HID * PIX + pix;
#pragma unroll
        for (int oc = 0; oc < HID; oc++) op[oc * PIX] = acc[oc];
    }
}

// ---------------------------------------------------------------------------
// convz (VECTORIZED): tile 64x16, 4 px/thread; h = h_fixed + conv3x3(z).
// float4 hfix reads + h writes; GN partials; LAST BLOCK folds stats.
// Batches with g_bfast set skip everything. Fold sets sticky g_bfast.
// ---------------------------------------------------------------------------
__global__ void __launch_bounds__(256) convz_kernel(
    const float* __restrict__ w1, const float* __restrict__ gn_w,
    const float* __restrict__ gn_b, int check)
{
    if (check && g_converged) return;
    const int b = blockIdx.z;
    const int tx0 = blockIdx.x * 64, ty0 = blockIdx.y * 16;
    __shared__ __align__(16) float s_z[18][68];   // 66 used, pitch 68 (16B-mult)
    __shared__ float s_w[9][32];
    __shared__ float s_red[8][8];
    __shared__ int s_rz[32];
    __shared__ bool s_last;
    __shared__ bool s_bf;
    int tid = threadIdx.y * 16 + threadIdx.x;

    if (tid == 0) s_bf = (g_bfast[b] != 0);
    __syncthreads();

    if (!s_bf) {
        for (int i = tid; i < HID * 9; i += 256) {
            int oc = i / 9, r = i % 9;
            s_w[r][oc] = w1[oc * 36 + r];       // z-channel taps (c=0)
        }

        const float* zp = g_z + b * PIX;
        for (int i = tid; i < 18 * 66; i += 256) {
            int yy = i / 66, xx = i % 66;
            int gy = ty0 + yy - 1, gx = tx0 + xx - 1;
            float v = 0.f;
            if ((unsigned)gy < 256u && (unsigned)gx < 256u)
                v = zp[gy * WW + gx];
            s_z[yy][xx] = v;
        }
        __syncthreads();

        int ty = threadIdx.y, tx = threadIdx.x;
        // 6 z values per row x 3 rows (cols 4tx .. 4tx+5 of halo)
        float zs[3][6];
#pragma unroll
        for (int ky = 0; ky < 3; ky++) {
            float4 z0 = *(const float4*)&s_z[ty + ky][4 * tx];
            zs[ky][0] = z0.x; zs[ky][1] = z0.y; zs[ky][2] = z0.z; zs[ky][3] = z0.w;
            zs[ky][4] = s_z[ty + ky][4 * tx + 4];
            zs[ky][5] = s_z[ty + ky][4 * tx + 5];
        }

        int pix = (ty0 + ty) * WW + tx0 + 4 * tx;
        const float* fp = g_hfix + (size_t)b * HID * PIX + pix;
        float* hp = g_h + (size_t)b * HID * PIX + pix;
        float gs[4] = {0, 0, 0, 0}, gq[4] = {0, 0, 0, 0};

#pragma unroll
        for (int chunk = 0; chunk < 4; chunk++) {
            float4 acc[8];
#pragma unroll
            for (int c = 0; c < 8; c++)
                acc[c] = *(const float4*)(fp + (chunk * 8 + c) * PIX);
#pragma unroll
            for (int ky = 0; ky < 3; ky++)
#pragma unroll
                for (int kx = 0; kx < 3; kx++) {
                    int r = ky * 3 + kx;
#pragma unroll
                    for (int c = 0; c < 8; c++) {
                        float w = s_w[r][chunk * 8 + c];
                        acc[c].x += zs[ky][kx + 0] * w;
                        acc[c].y += zs[ky][kx + 1] * w;
                        acc[c].z += zs[ky][kx + 2] * w;
                        acc[c].w += zs[ky][kx + 3] * w;
                    }
                }
            int g = chunk;                    // oc>>3 for oc in [chunk*8, chunk*8+8)
#pragma unroll
            for (int c = 0; c < 8; c++) {
                *(float4*)(hp + (chunk * 8 + c) * PIX) = acc[c];
                float4 v = acc[c];
                gs[g] += ((v.x + v.y) + (v.z + v.w));
                gq[g] += ((v.x * v.x + v.y * v.y) + (v.z * v.z + v.w * v.w));
            }
        }

#pragma unroll
        for (int o = 16; o > 0; o >>= 1) {
#pragma unroll
            for (int g = 0; g < 4; g++) {
                gs[g] += __shfl_down_sync(0xffffffffu, gs[g], o);
                gq[g] += __shfl_down_sync(0xffffffffu, gq[g], o);
            }
        }
        int lane = tid & 31, warp = tid >> 5;
        if (lane == 0) {
#pragma unroll
            for (int g = 0; g < 4; g++) { s_red[warp][g] = gs[g]; s_red[warp][4 + g] = gq[g]; }
        }
        __syncthreads();
        int blin = blockIdx.y * 4 + blockIdx.x;   // gridDim.x = 4
        if (tid < 8) {
            float v = 0.f;
#pragma unroll
            for (int w = 0; w < 8; w++) v += s_red[w][tid];
            int g = tid & 3, which = tid >> 2;
            g_part[((b * NBZ + blin) * 4 + g) * 2 + which] = v;
            __threadfence();
        }
        __syncthreads();
    }

    if (tid == 0) {
        unsigned old = atomicInc(&g_cnt1, NBLK_Z - 1u);
        s_last = (old == NBLK_Z - 1u);
    }
    __syncthreads();
    if (!s_last) return;
    __threadfence();

    // last block: fold GN stats for all 32 (b,g) pairs; 8 lanes per pair.
    // bb == warp id, so the g_bfast guard is warp-uniform.
    int pair = tid >> 3, l8 = tid & 7;
    int bb = pair >> 2, g = pair & 3;
    if (g_bfast[bb] == 0) {
        float s = 0.f, q = 0.f;
        for (int i = l8; i < NBZ; i += 8) {
            s += g_part[((bb * NBZ + i) * 4 + g) * 2 + 0];
            q += g_part[((bb * NBZ + i) * 4 + g) * 2 + 1];
        }
#pragma unroll
        for (int o = 4; o > 0; o >>= 1) {
            s += __shfl_down_sync(0xffffffffu, s, o, 8);
            q += __shfl_down_sync(0xffffffffu, q, o, 8);
        }
        if (l8 == 0) {
            const float invN = 1.0f / (float)(CPG * PIX);
            float mean = s * invN;
            float Qn = q * invN;
            float var = isinf(Qn) ? Qn : fmaxf(Qn - mean * mean, 0.0f);
            float rstd = rsqrtf(var + EPS);       // var=inf -> rstd=0
#pragma unroll
            for (int c = 0; c < CPG; c++) {
                int gc = g * CPG + c;
                float sc = gn_w[gc] * rstd;
                g_scale[bb * HID + gc] = sc;
                g_shift[bb * HID + gc] = (rstd == 0.0f) ? gn_b[gc] : (gn_b[gc] - mean * sc);
            }
            s_rz[pair] = (rstd == 0.0f);
        }
    } else if (l8 == 0) {
        s_rz[pair] = 1;                           // already fast: stays fast
    }
    __syncthreads();
    if (tid < BATCH) {
        if (s_rz[tid * 4 + 0] && s_rz[tid * 4 + 1] &&
            s_rz[tid * 4 + 2] && s_rz[tid * 4 + 3])
            g_bfast[tid] = 1;                     // sticky
    }
}

// ---------------------------------------------------------------------------
// fused2: GN->GELU->conv2(32->1)->damped update; LAST BLOCK folds diff.
// Tile 32x8, channel-PAIRED s_h + fma.rn.f32x2 conv loop.
// Normal path FILL8 staging; FAST path (all sc==0) = constant-dz shortcut.
// ---------------------------------------------------------------------------
// fill one halo pixel (yy,xx) for channels [base, base+8) into paired layout
#define FILL8(base, yy, xx, inb, hb)                                       \
    {                                                                      \
        float hv[8];                                                       \
        _Pragma("unroll")                                                  \
        for (int c = 0; c < 8; c++)                                        \
            hv[c] = (inb) ? (hb)[(base + c) * PIX] : 0.f;                  \
        _Pragma("unroll")                                                  \
        for (int c = 0; c < 8; c++) {                                      \
            float sc = s_sc[base + c];                                     \
            float t = (sc == 0.0f) ? s_sf[base + c]                        \
                                   : (hv[c] * sc + s_sf[base + c]);        \
            s_h[(base + c) >> 1][yy][xx][(base + c) & 1] =                 \
                (inb) ? gelu_f(t) : 0.f;                                   \
        }                                                                  \
    }

__global__ void __launch_bounds__(256, 3) fused2_kernel(
    const float* __restrict__ inp, const float* __restrict__ w2,
    const float* __restrict__ b2, float* __restrict__ final_out, int mode)
{
    if (mode == 0 && g_converged) return;
    const int b = blockIdx.z;
    const int tx0 = blockIdx.x * 32, ty0 = blockIdx.y * 8;
    __shared__ __align__(8) float s_h[16][10][34][2];   // channel-paired
    __shared__ __align__(8) float s_wp[9][16][2];       // [pos][c2][elem]
    __shared__ float s_sc[HID], s_sf[HID];
    __shared__ float s_G[HID];
    __shared__ float s_red[8];
    __shared__ float s_Dfull;
    __shared__ bool s_fast;
    __shared__ bool s_last;
    int tid = threadIdx.y * 32 + threadIdx.x;

    for (int i = tid; i < HID * 9; i += 256) {
        int c = i / 9, pos = i % 9;
        s_wp[pos][c >> 1][c & 1] = w2[i];
    }
    if (tid < HID) { s_sc[tid] = g_scale[b * HID + tid]; s_sf[tid] = g_shift[b * HID + tid]; }
    __syncthreads();

    // warp 0: overflow fast-path detection + constant-G precompute
    if (tid < 32) {
        int zero = (s_sc[tid] == 0.0f);
        unsigned bal = __ballot_sync(0xffffffffu, zero);
        float wsum = 0.f;
#pragma unroll
        for (int j = 0; j < 9; j++) wsum += s_wp[j][tid >> 1][tid & 1];
        float Gc = gelu_f(s_sf[tid]);     // == gelu(gn_b) when sc==0
        s_G[tid] = Gc;
        float t = Gc * wsum;
#pragma unroll
        for (int o = 16; o > 0; o >>= 1) t += __shfl_down_sync(0xffffffffu, t, o);
        if (tid == 0) { s_fast = (bal == 0xffffffffu); s_Dfull = t; }
    }
    __syncthreads();

    int ty = threadIdx.y, tx = threadIdx.x;
    float acc;

    if (s_fast) {
        // all sc==0: G constant per channel; dz depends only on valid-tap mask
        int Y = ty0 + ty, X = tx0 + tx;
        bool interior = (Y >= 1) && (Y <= 254) && (X >= 1) && (X <= 254);
        if (interior) {
            acc = b2[0] + s_Dfull;
        } else {
            acc = b2[0];
            int ky0 = (Y == 0) ? 1 : 0, ky1 = (Y == 255) ? 2 : 3;
            int kx0 = (X == 0) ? 1 : 0, kx1 = (X == 255) ? 2 : 3;
            for (int c = 0; c < HID; c++) {
                float wsum = 0.f;
                for (int ky = ky0; ky < ky1; ky++)
                    for (int kx = kx0; kx < kx1; kx++)
                        wsum += s_wp[ky * 3 + kx][c >> 1][c & 1];
                acc += s_G[c] * wsum;
            }
        }
    } else {
        const float* hp = g_h + (size_t)b * HID * PIX;
        {
            // halo = 10 rows x 34 cols = 340 pixels
            // pixel 1: p = tid (tid < 340 always)
            int yy = tid / 34, xx = tid % 34;
            int gy = ty0 + yy - 1, gx = tx0 + xx - 1;
            bool inb = ((unsigned)gy < 256u) && ((unsigned)gx < 256u);
            const float* hb = hp + (inb ? (gy * WW + gx) : 0);
            FILL8(0, yy, xx, inb, hb)
            FILL8(8, yy, xx, inb, hb)
            FILL8(16, yy, xx, inb, hb)
            FILL8(24, yy, xx, inb, hb)
            // pixel 2: p = tid + 256 (only tid < 84)
            if (tid < 84) {
                int p2 = tid + 256;
                int yy2 = p2 / 34, xx2 = p2 % 34;
                int gy2 = ty0 + yy2 - 1, gx2 = tx0 + xx2 - 1;
                bool inb2 = ((unsigned)gy2 < 256u) && ((unsigned)gx2 < 256u);
                const float* hb2 = hp + (inb2 ? (gy2 * WW + gx2) : 0);
                FILL8(0, yy2, xx2, inb2, hb2)
                FILL8(8, yy2, xx2, inb2, hb2)
                FILL8(16, yy2, xx2, inb2, hb2)
                FILL8(24, yy2, xx2, inb2, hb2)
            }
        }
        __syncthreads();

        // channel-paired conv: 144 LDS.64 + 144 bcast LDS.64 + 144 FFMA2
        unsigned long long pa[4] = {0ull, 0ull, 0ull, 0ull};
#pragma unroll
        for (int c2 = 0; c2 < 16; c2++) {
#pragma unroll
            for (int ky = 0; ky < 3; ky++)
#pragma unroll
                for (int kx = 0; kx < 3; kx++) {
                    int pos = ky * 3 + kx;
                    unsigned long long h2 =
                        *(const unsigned long long*)&s_h[c2][ty + ky][tx + kx][0];
                    unsigned long long w2p =
                        *(const unsigned long long*)&s_wp[pos][c2][0];
                    FMA2(pa[(c2 * 9 + pos) & 3], h2, w2p);
                }
        }
        float lo0, hi0, lo1, hi1, lo2, hi2, lo3, hi3;
        UNPACK2(lo0, hi0, pa[0]);
        UNPACK2(lo1, hi1, pa[1]);
        UNPACK2(lo2, hi2, pa[2]);
        UNPACK2(lo3, hi3, pa[3]);
        acc = b2[0] + (((lo0 + hi0) + (lo1 + hi1)) + ((lo2 + hi2) + (lo3 + hi3)));
    }

    int pix = (ty0 + ty) * WW + (tx0 + tx);
    int off = b * PIX + pix;
    const float* bp = inp + (size_t)b * 3 * PIX;
    float zold = g_z[off];
    // mirror XLA elementwise rounding exactly (no FMA contraction)
    float ga   = __fmul_rn(g_gamma[b], g_alpha[off]);
    float znew = __fadd_rn(zold, __fmul_rn(ga, acc));
    float m  = bp[PIX + pix];
    float bv = bp[pix];
    float res = __fadd_rn(__fmul_rn(znew, __fadd_rn(1.0f, -m)), __fmul_rn(bv, m));

    if (mode != 0) { final_out[off] = res; return; }

    g_z[off] = res;
    float d = __fadd_rn(res, -zold);
    float s = d * d;
#pragma unroll
    for (int o = 16; o > 0; o >>= 1) s += __shfl_down_sync(0xffffffffu, s, o);
    int lane = tid & 31, warp = tid >> 5;
    if (lane == 0) s_red[warp] = s;
    __syncthreads();
    int blin = blockIdx.y * 8 + blockIdx.x;   // grid (8, 32): 256 blocks/batch
    if (tid == 0) {
        float t = 0.f;
#pragma unroll
        for (int w = 0; w < 8; w++) t += s_red[w];
        g_diffpart[b * 256 + blin] = t;
        __threadfence();
        unsigned old = atomicInc(&g_cnt2, NBLK - 1u);
        s_last = (old == NBLK - 1u);
    }
    __syncthreads();
    if (!s_last) return;
    __threadfence();

    // last block: diff = mean_b ||dz_b||; jax cond continues while diff>=TOL
    int w = tid >> 5, l = tid & 31;
    float t = 0.f;
    for (int i = l; i < 256; i += 32) t += g_diffpart[w * 256 + i];
#pragma unroll
    for (int o = 16; o > 0; o >>= 1) t += __shfl_down_sync(0xffffffffu, t, o);
    __shared__ float sb[8];
    if (l == 0) sb[w] = sqrtf(t);
    __syncthreads();
    if (tid == 0) {
        float mm = 0.f;
#pragma unroll
        for (int bb = 0; bb < 8; bb++) mm += sb[bb];
        mm *= 0.125f;
        if (!(mm >= TOL)) g_converged = 1;   // NaN also stops (matches jax)
    }
}

// ---------------------------------------------------------------------------
extern "C" void kernel_launch(void* const* d_in, const int* in_sizes, int n_in,
                              void* d_out, int out_size)
{
    const float* inp     = (const float*)d_in[0];
    const float* core_w1 = (const float*)d_in[1];
    const float* core_b1 = (const float*)d_in[2];
    const float* gn_w    = (const float*)d_in[3];
    const float* gn_b    = (const float*)d_in[4];
    const float* core_w2 = (const float*)d_in[5];
    const float* core_b2 = (const float*)d_in[6];
    const float* stab_w1 = (const float*)d_in[7];
    const float* stab_b1 = (const float*)d_in[8];
    const float* stab_w2 = (const float*)d_in[9];
    const float* stab_b2 = (const float*)d_in[10];
    const float* fc1_w   = (const float*)d_in[11];
    const float* fc1_b   = (const float*)d_in[12];
    const float* fc2_w   = (const float*)d_in[13];
    const float* fc2_b   = (const float*)d_in[14];
    float* out = (float*)d_out;

    dim3 blk(16, 16);
    dim3 grd(16, 16, BATCH);
    dim3 blkF(32, 8);
    dim3 grdF(8, 32, BATCH);      // fused2: 32x8 tiles
    dim3 grdZ(4, 16, BATCH);      // convz: 64x16 tiles, 4 px/thread

    // convz is the 3rd launch; fused2 the 4th (ncu capture window)
    stab1_kernel<<<grd, blk>>>(inp, stab_w1, stab_b1, fc1_w, fc1_b, fc2_w, fc2_b);
    prep_kernel<<<grd, blk>>>(inp, stab_w2, stab_b2, core_w1, core_b1);
    convz_kernel<<<grdZ, blk>>>(core_w1, gn_w, gn_b, 1);
    fused2_kernel<<<grdF, blkF>>>(inp, core_w2, core_b2, nullptr, 0);

    for (int it = 1; it < MAX_ITER; ++it) {
        convz_kernel<<<grdZ, blk>>>(core_w1, gn_w, gn_b, 1);
        fused2_kernel<<<grdF, blkF>>>(inp, core_w2, core_b2, nullptr, 0);
    }
    // final core_f (always runs): z_star -> d_out
    convz_kernel<<<grdZ, blk>>>(core_w1, gn_w, gn_b, 0);
    fused2_kernel<<<grdF, blkF>>>(inp, core_w2, core_b2, out, 1);
}